// round 11
// baseline (speedup 1.0000x reference)
#include <cuda_runtime.h>
#include <cuda_bf16.h>
#include <cstdint>
#include <math.h>

// Shapes (fixed per problem)
#define B_   256
#define X_   512
#define H_   1024
#define M_   128
#define KK_  64
#define XH   1536      // X + H
#define XCU  1664      // X + H + M
#define XC2  2560      // X + 2H
#define HQ   256       // H/4
#define N5   5120      // 5H
#define N2   2048      // 2H
#define EPS  1e-5f

// ---------------- scratch ----------------
__device__ float g_sbase[B_ * HQ];
__device__ float g_kpart[M_ * HQ];
__device__ float g_score[B_ * M_];
__device__ float g_hentry[B_ * H_];
__device__ float g_concat[B_ * XC2];
__device__ __nv_bfloat16 g_ch[B_ * XC2];   // concat bf16 hi
__device__ __nv_bfloat16 g_cl[B_ * XC2];   // concat bf16 lo
__device__ float g_xcu[B_ * XCU];
__device__ float g_part[4 * B_ * N5];      // also covers 8*B_*N2
// bf16 hi/lo transposed weights [N, K]
__device__ __nv_bfloat16 g_Whh[HQ * H_];
__device__ __nv_bfloat16 g_Whl[HQ * H_];
__device__ __nv_bfloat16 g_W1h[N2 * XC2];
__device__ __nv_bfloat16 g_W1l[N2 * XC2];
__device__ __nv_bfloat16 g_Wfh[N5 * XC2];
__device__ __nv_bfloat16 g_Wfl[N5 * XC2];

// ---------------- low-level helpers ----------------
__device__ __forceinline__ uint32_t smem_u32(const void* p) {
    uint32_t a;
    asm("{ .reg .u64 t; cvta.to.shared.u64 t, %1; cvt.u32.u64 %0, t; }" : "=r"(a) : "l"(p));
    return a;
}
__device__ __forceinline__ void ldsm4(uint32_t* r, uint32_t a) {
    asm volatile("ldmatrix.sync.aligned.m8n8.x4.shared.b16 {%0,%1,%2,%3}, [%4];"
                 : "=r"(r[0]), "=r"(r[1]), "=r"(r[2]), "=r"(r[3]) : "r"(a));
}
__device__ __forceinline__ void mma16816(float* c, const uint32_t* a, const uint32_t* b) {
    asm volatile("mma.sync.aligned.m16n8k16.row.col.f32.bf16.bf16.f32 "
                 "{%0,%1,%2,%3}, {%4,%5,%6,%7}, {%8,%9}, {%0,%1,%2,%3};"
                 : "+f"(c[0]), "+f"(c[1]), "+f"(c[2]), "+f"(c[3])
                 : "r"(a[0]), "r"(a[1]), "r"(a[2]), "r"(a[3]), "r"(b[0]), "r"(b[1]));
}
__device__ __forceinline__ void cpa16(uint32_t dst, const void* src) {
    asm volatile("cp.async.cg.shared.global [%0], [%1], 16;" :: "r"(dst), "l"(src));
}
#define CP_COMMIT() asm volatile("cp.async.commit_group;" ::: "memory")
#define CP_WAIT1()  asm volatile("cp.async.wait_group 1;" ::: "memory")
#define CP_WAIT0()  asm volatile("cp.async.wait_group 0;" ::: "memory")

__device__ __forceinline__ uint32_t pack_hi2(float x, float y, float& lx, float& ly) {
    __nv_bfloat162 h = __floats2bfloat162_rn(x, y);
    lx = x - __bfloat162float(h.x);
    ly = y - __bfloat162float(h.y);
    return *(uint32_t*)&h;
}
__device__ __forceinline__ uint32_t pack2(float x, float y) {
    __nv_bfloat162 h = __floats2bfloat162_rn(x, y);
    return *(uint32_t*)&h;
}
__device__ __forceinline__ float sigm(float x) { return 1.0f / (1.0f + expf(-x)); }

__device__ __forceinline__ float brsum(float v, float* red) {
    int lane = threadIdx.x & 31, w = threadIdx.x >> 5;
    int nw = blockDim.x >> 5;
    #pragma unroll
    for (int o = 16; o; o >>= 1) v += __shfl_xor_sync(0xffffffffu, v, o);
    __syncthreads();
    if (lane == 0) red[w] = v;
    __syncthreads();
    float s = 0.f;
    for (int i = 0; i < nw; i++) s += red[i];
    return s;
}
// write fp32 value as bf16 hi/lo pair
__device__ __forceinline__ void split_store(float v, __nv_bfloat16* hi, __nv_bfloat16* lo) {
    __nv_bfloat16 h = __float2bfloat16(v);
    *hi = h;
    *lo = __float2bfloat16(v - __bfloat162float(h));
}

// ---------------- weight transpose + bf16 hi/lo split ----------------
__global__ void wconv(const float* __restrict__ W, int K, int N, int which)
{
    __nv_bfloat16 *Whi, *Wlo;
    if (which == 0)      { Whi = g_Whh; Wlo = g_Whl; }
    else if (which == 1) { Whi = g_W1h; Wlo = g_W1l; }
    else                 { Whi = g_Wfh; Wlo = g_Wfl; }
    __shared__ float t[64][33];
    int nb = blockIdx.x * 32, kb = blockIdx.y * 64;
    int tx = threadIdx.x, ty = threadIdx.y;
    for (int r = ty; r < 64; r += 8)
        t[r][tx] = W[(size_t)(kb + r) * N + nb + tx];
    __syncthreads();
    for (int r = ty; r < 32; r += 8) {
        float v0 = t[2 * tx][r], v1 = t[2 * tx + 1][r];
        float l0, l1;
        uint32_t hp = pack_hi2(v0, v1, l0, l1);
        uint32_t lp = pack2(l0, l1);
        size_t o = (size_t)(nb + r) * K + kb + 2 * tx;
        *(uint32_t*)&Whi[o] = hp;
        *(uint32_t*)&Wlo[o] = lp;
    }
}

// ---------------- K1a: build g_xcu = [x | c | u_norm] ----------------
__global__ void k1a_xcu(const float* __restrict__ x, const float* __restrict__ c,
                        const float* __restrict__ u_t)
{
    int b = blockIdx.x, t = threadIdx.x;  // 128 threads
    __shared__ float red[4];
    float uv = u_t[b * M_ + t];
    float s = brsum(uv * uv, red);
    float inv = 1.0f / fmaxf(sqrtf(s), 1e-12f);
    float* row = g_xcu + (size_t)b * XCU;
    for (int i = t; i < X_; i += 128) row[i] = x[b * X_ + i];
    for (int i = t; i < H_; i += 128) row[X_ + i] = c[b * H_ + i];
    row[XH + t] = uv * inv;
}

// ---------------- K1b: split-K SGEMM  g_part[z] = g_xcu[:,ks] @ fc_w'[ks,:] ----------------
__global__ __launch_bounds__(256) void k1b_sgemm(const float* __restrict__ fc_w)
{
    __shared__ float As[16][64];
    __shared__ float Bs[16][256];
    int rowBase = blockIdx.x * 64;
    int kStart = blockIdx.y * 208;
    int tx = threadIdx.x, ty = threadIdx.y;
    int tid = ty * 32 + tx;

    float acc[8][8];
    #pragma unroll
    for (int i = 0; i < 8; i++)
        #pragma unroll
        for (int j = 0; j < 8; j++) acc[i][j] = 0.f;

    int am = tid >> 2;
    int ak = (tid & 3) * 4;
    int bc = (tid & 63) * 4;
    int br0 = tid >> 6;

    for (int k0 = 0; k0 < 208; k0 += 16) {
        float4 av = *(const float4*)&g_xcu[(size_t)(rowBase + am) * XCU + kStart + k0 + ak];
        As[ak + 0][am] = av.x; As[ak + 1][am] = av.y;
        As[ak + 2][am] = av.z; As[ak + 3][am] = av.w;
        #pragma unroll
        for (int r = 0; r < 4; r++) {
            int kk = r * 4 + br0;
            int krow = kStart + k0 + kk;
            int frow = (krow < XH) ? krow : krow + 1088;   // u segment -> fc_w rows 2624+
            *(float4*)&Bs[kk][bc] = *(const float4*)&fc_w[(size_t)frow * HQ + bc];
        }
        __syncthreads();
        #pragma unroll
        for (int k = 0; k < 16; k++) {
            float4 a0 = *(float4*)&As[k][ty * 8];
            float4 a1 = *(float4*)&As[k][ty * 8 + 4];
            float4 b0 = *(float4*)&Bs[k][tx * 8];
            float4 b1 = *(float4*)&Bs[k][tx * 8 + 4];
            float a[8] = {a0.x, a0.y, a0.z, a0.w, a1.x, a1.y, a1.z, a1.w};
            float b[8] = {b0.x, b0.y, b0.z, b0.w, b1.x, b1.y, b1.z, b1.w};
            #pragma unroll
            for (int i = 0; i < 8; i++)
                #pragma unroll
                for (int j = 0; j < 8; j++)
                    acc[i][j] = fmaf(a[i], b[j], acc[i][j]);
        }
        __syncthreads();
    }

    float* P = g_part + (size_t)blockIdx.y * B_ * HQ;
    #pragma unroll
    for (int i = 0; i < 8; i++) {
        int row = rowBase + ty * 8 + i;
        *(float4*)&P[(size_t)row * HQ + tx * 8]     = make_float4(acc[i][0], acc[i][1], acc[i][2], acc[i][3]);
        *(float4*)&P[(size_t)row * HQ + tx * 8 + 4] = make_float4(acc[i][4], acc[i][5], acc[i][6], acc[i][7]);
    }
}

// ---------------- K1c: reduce 8 partials + fc_b -> g_sbase ----------------
__global__ void k1c_red(const float* __restrict__ fc_b)
{
    int b = blockIdx.x, j = threadIdx.x;
    float a = fc_b[j];
    #pragma unroll
    for (int z = 0; z < 8; z++) a += g_part[((size_t)z * B_ + b) * HQ + j];
    g_sbase[b * HQ + j] = a;
}

// ================= K3: score GEMM (bf16x3) =================
// tile 128x256, BK=32, 512 threads (16 warps, 4x4), warp 32x64. stride 80 B.
#define K3_AH(b) ((b) * 10240)
#define K3_AL(b) (20480 + (b) * 10240)
#define K3_BH(b) (40960 + (b) * 20480)
#define K3_BL(b) (81920 + (b) * 20480)
#define K3_RED   122880
#define K3_SMEM  124928

__global__ __launch_bounds__(512, 1) void k3_mma(
    const float* __restrict__ hmem, const float* __restrict__ vec_a)
{
    extern __shared__ char sm[];
    uint32_t sb = smem_u32(sm);
    int tid = threadIdx.x, lane = tid & 31, wid = tid >> 5;
    int wm = wid & 3, wn = wid >> 2;   // 4 x 4 warps
    int rowBase = blockIdx.x * 128;

    float acc[2][8][4];
    #pragma unroll
    for (int i = 0; i < 2; i++)
        #pragma unroll
        for (int j = 0; j < 8; j++)
            #pragma unroll
            for (int q = 0; q < 4; q++) acc[i][j][q] = 0.f;

    auto loadA = [&](int i, int buf) {
        int c0 = i * 32;
        #pragma unroll
        for (int it = 0; it < 2; it++) {
            int idx = tid + it * 512;
            int row = idx >> 3, q = idx & 7;
            float4 v = *(const float4*)&hmem[(size_t)(rowBase + row) * H_ + c0 + q * 4];
            float lx, ly, lz, lw;
            uint32_t h0 = pack_hi2(v.x, v.y, lx, ly);
            uint32_t h1 = pack_hi2(v.z, v.w, lz, lw);
            char* ah = sm + K3_AH(buf) + row * 80 + q * 8;
            char* al = sm + K3_AL(buf) + row * 80 + q * 8;
            *(uint32_t*)ah = h0; *(uint32_t*)(ah + 4) = h1;
            *(uint32_t*)al = pack2(lx, ly); *(uint32_t*)(al + 4) = pack2(lz, lw);
        }
    };
    auto loadB = [&](int i, int buf) {
        int c0 = i * 32;
        #pragma unroll
        for (int it = 0; it < 2; it++) {
            int idx = tid + it * 512;
            int row = idx >> 2, seg = idx & 3;
            cpa16(sb + K3_BH(buf) + row * 80 + seg * 16, g_Whh + (size_t)row * H_ + c0 + seg * 8);
            cpa16(sb + K3_BL(buf) + row * 80 + seg * 16, g_Whl + (size_t)row * H_ + c0 + seg * 8);
        }
    };

    const int niter = H_ / 32;   // 32
    loadA(0, 0); loadB(0, 0); CP_COMMIT();

    uint32_t aoffA = (uint32_t)((lane & 15) * 80 + (lane >> 4) * 16);
    uint32_t aoffB = (uint32_t)(((lane & 7) + ((lane >> 4) << 3)) * 80 + (((lane >> 3) & 1) << 4));

    for (int i = 0; i < niter; i++) {
        int buf = i & 1;
        if (i + 1 < niter) { loadA(i + 1, buf ^ 1); loadB(i + 1, buf ^ 1); CP_COMMIT(); CP_WAIT1(); }
        else CP_WAIT0();
        __syncthreads();

        #pragma unroll
        for (int ks = 0; ks < 2; ks++) {
            uint32_t kso = (uint32_t)(ks * 32);
            uint32_t aH[2][4], aL[2][4], bH[8][2], bL[8][2];
            #pragma unroll
            for (int mt = 0; mt < 2; mt++) {
                uint32_t ro = (uint32_t)((wm * 32 + mt * 16) * 80) + kso;
                ldsm4(aH[mt], sb + K3_AH(buf) + ro + aoffA);
                ldsm4(aL[mt], sb + K3_AL(buf) + ro + aoffA);
            }
            #pragma unroll
            for (int p = 0; p < 4; p++) {
                uint32_t ro = (uint32_t)((wn * 64 + p * 16) * 80) + kso;
                uint32_t t4[4];
                ldsm4(t4, sb + K3_BH(buf) + ro + aoffB);
                bH[2*p][0] = t4[0]; bH[2*p][1] = t4[1]; bH[2*p+1][0] = t4[2]; bH[2*p+1][1] = t4[3];
                ldsm4(t4, sb + K3_BL(buf) + ro + aoffB);
                bL[2*p][0] = t4[0]; bL[2*p][1] = t4[1]; bL[2*p+1][0] = t4[2]; bL[2*p+1][1] = t4[3];
            }
            #pragma unroll
            for (int mt = 0; mt < 2; mt++)
                #pragma unroll
                for (int nt = 0; nt < 8; nt++) {
                    mma16816(acc[mt][nt], aH[mt], bH[nt]);
                    mma16816(acc[mt][nt], aL[mt], bH[nt]);
                    mma16816(acc[mt][nt], aH[mt], bL[nt]);
                }
        }
        __syncthreads();
    }

    // epilogue: + sbase + kpart, tanh, dot vec_a, reduce over 256 cols
    float* sred = (float*)(sm + K3_RED);   // [128][4]
    int bi = rowBase >> 7;
    const float* sb_row = g_sbase + bi * HQ;
    #pragma unroll
    for (int mt = 0; mt < 2; mt++) {
        #pragma unroll
        for (int h = 0; h < 2; h++) {
            int rl = wm * 32 + mt * 16 + (lane >> 2) + h * 8;  // 0..127 = m index
            const float* kp_row = g_kpart + rl * HQ;
            float rsum = 0.f;
            #pragma unroll
            for (int nt = 0; nt < 8; nt++) {
                #pragma unroll
                for (int j = 0; j < 2; j++) {
                    int col = wn * 64 + nt * 8 + (lane & 3) * 2 + j;
                    float v = acc[mt][nt][h * 2 + j] + sb_row[col] + kp_row[col];
                    rsum = fmaf(tanhf(v), vec_a[col], rsum);
                }
            }
            rsum += __shfl_xor_sync(0xffffffffu, rsum, 1);
            rsum += __shfl_xor_sync(0xffffffffu, rsum, 2);
            if ((lane & 3) == 0) sred[rl * 4 + wn] = rsum;
        }
    }
    __syncthreads();
    if (tid < 128)
        g_score[rowBase + tid] = sred[tid * 4] + sred[tid * 4 + 1]
                               + sred[tid * 4 + 2] + sred[tid * 4 + 3];
}

// ================= z GEMMs: bf16x3, A pre-split (pure cp.async loads) =================
#define ZG_AH(b) ((b) * 10240)
#define ZG_AL(b) (20480 + (b) * 10240)
#define ZG_BH(b) (40960 + (b) * 10240)
#define ZG_BL(b) (61440 + (b) * 10240)
#define ZG_SMEM  81920

__global__ __launch_bounds__(256, 2) void gemm_z(int which, int Nfull, int kslice)
{
    extern __shared__ char sm[];
    uint32_t sb = smem_u32(sm);
    const __nv_bfloat16 *Bh, *Bl;
    if (which == 1) { Bh = g_W1h; Bl = g_W1l; }
    else            { Bh = g_Wfh; Bl = g_Wfl; }
    int tid = threadIdx.x, lane = tid & 31, wid = tid >> 5;
    int wm = wid & 3, wn = wid >> 2;
    int rowBase = blockIdx.y * 128;
    int colBase = blockIdx.x * 128;
    int kStart  = blockIdx.z * kslice;

    float acc[2][8][4];
    #pragma unroll
    for (int i = 0; i < 2; i++)
        #pragma unroll
        for (int j = 0; j < 8; j++)
            #pragma unroll
            for (int q = 0; q < 4; q++) acc[i][j][q] = 0.f;

    auto loadA = [&](int i, int buf) {
        int c0 = kStart + i * 32;
        #pragma unroll
        for (int it = 0; it < 2; it++) {
            int idx = tid + it * 256;
            int row = idx >> 2, seg = idx & 3;
            size_t src = (size_t)(rowBase + row) * XC2 + c0 + seg * 8;
            cpa16(sb + ZG_AH(buf) + row * 80 + seg * 16, g_ch + src);
            cpa16(sb + ZG_AL(buf) + row * 80 + seg * 16, g_cl + src);
        }
    };
    auto loadB = [&](int i, int buf) {
        int c0 = kStart + i * 32;
        #pragma unroll
        for (int it = 0; it < 2; it++) {
            int idx = tid + it * 256;
            int row = idx >> 2, seg = idx & 3;
            size_t src = (size_t)(colBase + row) * XC2 + c0 + seg * 8;
            cpa16(sb + ZG_BH(buf) + row * 80 + seg * 16, Bh + src);
            cpa16(sb + ZG_BL(buf) + row * 80 + seg * 16, Bl + src);
        }
    };

    const int niter = kslice / 32;
    loadA(0, 0); loadB(0, 0); CP_COMMIT();

    uint32_t aoffA = (uint32_t)((lane & 15) * 80 + (lane >> 4) * 16);
    uint32_t aoffB = (uint32_t)(((lane & 7) + ((lane >> 4) << 3)) * 80 + (((lane >> 3) & 1) << 4));

    for (int i = 0; i < niter; i++) {
        int buf = i & 1;
        if (i + 1 < niter) { loadA(i + 1, buf ^ 1); loadB(i + 1, buf ^ 1); CP_COMMIT(); CP_WAIT1(); }
        else CP_WAIT0();
        __syncthreads();

        #pragma unroll
        for (int ks = 0; ks < 2; ks++) {
            uint32_t kso = (uint32_t)(ks * 32);
            uint32_t aH[2][4], aL[2][4], bH[8][2], bL[8][2];
            #pragma unroll
            for (int mt = 0; mt < 2; mt++) {
                uint32_t ro = (uint32_t)((wm * 32 + mt * 16) * 80) + kso;
                ldsm4(aH[mt], sb + ZG_AH(buf) + ro + aoffA);
                ldsm4(aL[mt], sb + ZG_AL(buf) + ro + aoffA);
            }
            #pragma unroll
            for (int p = 0; p < 4; p++) {
                uint32_t ro = (uint32_t)((wn * 64 + p * 16) * 80) + kso;
                uint32_t t4[4];
                ldsm4(t4, sb + ZG_BH(buf) + ro + aoffB);
                bH[2*p][0] = t4[0]; bH[2*p][1] = t4[1]; bH[2*p+1][0] = t4[2]; bH[2*p+1][1] = t4[3];
                ldsm4(t4, sb + ZG_BL(buf) + ro + aoffB);
                bL[2*p][0] = t4[0]; bL[2*p][1] = t4[1]; bL[2*p+1][0] = t4[2]; bL[2*p+1][1] = t4[3];
            }
            #pragma unroll
            for (int mt = 0; mt < 2; mt++)
                #pragma unroll
                for (int nt = 0; nt < 8; nt++) {
                    mma16816(acc[mt][nt], aH[mt], bH[nt]);
                    mma16816(acc[mt][nt], aL[mt], bH[nt]);
                    mma16816(acc[mt][nt], aH[mt], bL[nt]);
                }
        }
        __syncthreads();
    }

    float* P = g_part + (size_t)blockIdx.z * B_ * Nfull;
    int row0 = rowBase + wm * 32;
    int col0 = colBase + wn * 64;
    #pragma unroll
    for (int mt = 0; mt < 2; mt++)
        #pragma unroll
        for (int nt = 0; nt < 8; nt++)
            #pragma unroll
            for (int h = 0; h < 2; h++) {
                int r = row0 + mt * 16 + (lane >> 2) + h * 8;
                int cc = col0 + nt * 8 + (lane & 3) * 2;
                *(float2*)&P[(size_t)r * Nfull + cc] =
                    make_float2(acc[mt][nt][h * 2], acc[mt][nt][h * 2 + 1]);
            }
}

// ---------------- K2: k_part ----------------
__global__ void k2_kpart(const float* __restrict__ keys, const float* __restrict__ fc_w)
{
    __shared__ float ks[KK_];
    int m = blockIdx.x, j = threadIdx.x;
    if (j < KK_) ks[j] = keys[m * KK_ + j];
    __syncthreads();
    float acc = 0.f;
    #pragma unroll 8
    for (int i = 0; i < KK_; i++) acc = fmaf(ks[i], fc_w[(XH + i) * HQ + j], acc);
    g_kpart[m * HQ + j] = acc;
}

// ---------------- K4: score LN + gumbel argmax + gather; build concat (fp32 + bf16 hi/lo) ----
__global__ void k4_read(
    const float* __restrict__ x, const float* __restrict__ c,
    const float* __restrict__ prev, const float* __restrict__ gu,
    const float* __restrict__ hmem,
    const float* __restrict__ ln4_g, const float* __restrict__ ln4_b)
{
    int b = blockIdx.x, t = threadIdx.x;
    __shared__ float red[4];
    __shared__ float redf[4];
    __shared__ int   redi[4];
    __shared__ float s_vmax;
    __shared__ int   s_arg;

    float s = g_score[b * M_ + t] - prev[b * M_ + t] * 100.0f;
    float mu = brsum(s, red) * (1.0f / 128.0f);
    float d = s - mu;
    float var = brsum(d * d, red) * (1.0f / 128.0f);
    float sn = d * rsqrtf(var + EPS) * ln4_g[t] + ln4_b[t];
    float u = gu[b * M_ + t];
    float gmb = -logf(1e-20f - logf(1e-20f + u));
    float v = sn + gmb;

    float bv = v; int bidx = t;
    #pragma unroll
    for (int o = 16; o; o >>= 1) {
        float ov = __shfl_xor_sync(0xffffffffu, bv, o);
        int   oi = __shfl_xor_sync(0xffffffffu, bidx, o);
        if (ov > bv || (ov == bv && oi < bidx)) { bv = ov; bidx = oi; }
    }
    __syncthreads();
    if ((t & 31) == 0) { redf[t >> 5] = bv; redi[t >> 5] = bidx; }
    __syncthreads();
    if (t == 0) {
        float fv = redf[0]; int fi = redi[0];
        for (int w = 1; w < 4; w++)
            if (redf[w] > fv || (redf[w] == fv && redi[w] < fi)) { fv = redf[w]; fi = redi[w]; }
        s_vmax = fv; s_arg = fi;
    }
    __syncthreads();
    float e = expf(v - s_vmax);
    float ssum = brsum(e, red);
    float ymax = 1.0f / ssum;
    float w = (1.0f - ymax) + ymax;
    int mi = s_arg;

    const float* hrow = hmem + ((size_t)b * M_ + mi) * H_;
    size_t base = (size_t)b * XC2;
    for (int i = t; i < H_; i += 128) {
        float hv = w * hrow[i];
        float cv = c[b * H_ + i];
        g_hentry[b * H_ + i] = hv;
        g_concat[base + XH + i] = hv;
        g_concat[base + X_ + i] = cv;
        split_store(hv, g_ch + base + XH + i, g_cl + base + XH + i);
        split_store(cv, g_ch + base + X_ + i, g_cl + base + X_ + i);
    }
    for (int i = t; i < X_; i += 128) {
        float xv = x[b * X_ + i];
        g_concat[base + i] = xv;
        split_store(xv, g_ch + base + i, g_cl + base + i);
    }
}

// ---------------- K6: reduce split-K(8) + bias1 + chunk-LN + sigmoid gate (updates hi/lo) ----
__global__ void k6_gate(
    const float* __restrict__ bias1,
    const float* __restrict__ ln3_g, const float* __restrict__ ln3_b)
{
    int ch = blockIdx.x, b = blockIdx.y;
    int t = threadIdx.x;
    __shared__ float red[8];
    float v[4];
    float sum = 0.f;
    #pragma unroll
    for (int q = 0; q < 4; q++) {
        int col = ch * 1024 + q * 256 + t;
        float a = 0.f;
        #pragma unroll
        for (int z = 0; z < 8; z++) a += g_part[((size_t)z * B_ + b) * N2 + col];
        a += bias1[col];
        v[q] = a; sum += a;
    }
    float mu = brsum(sum, red) * (1.0f / 1024.0f);
    float vs = 0.f;
    #pragma unroll
    for (int q = 0; q < 4; q++) { v[q] -= mu; vs += v[q] * v[q]; }
    float var = brsum(vs, red) * (1.0f / 1024.0f);
    float rs = rsqrtf(var + EPS);
    #pragma unroll
    for (int q = 0; q < 4; q++) {
        int col = ch * 1024 + q * 256 + t;
        float g1 = sigm(v[q] * rs * ln3_g[col] + ln3_b[col]);
        size_t o = (size_t)b * XC2 + X_ + col;
        float gated = g_concat[o] * g1;
        split_store(gated, g_ch + o, g_cl + o);
    }
}

// ---------------- K8 fused: reduce split-K(4) + bias + chunk-LN(5) + cell + LN + outputs ----
__global__ void k8_fused(
    const float* __restrict__ bias,
    const float* __restrict__ ln1_g, const float* __restrict__ ln1_b,
    const float* __restrict__ c,
    const float* __restrict__ ln2_g, const float* __restrict__ ln2_b,
    float* __restrict__ out)
{
    int b = blockIdx.x, t = threadIdx.x;   // 256 threads
    __shared__ float red[8];
    float zr[5][4];
    #pragma unroll
    for (int ch = 0; ch < 5; ch++) {
        float v[4];
        float sum = 0.f;
        #pragma unroll
        for (int q = 0; q < 4; q++) {
            int col = ch * 1024 + q * 256 + t;
            float a = 0.f;
            #pragma unroll
            for (int z = 0; z < 4; z++) a += g_part[((size_t)z * B_ + b) * N5 + col];
            a += bias[col];
            v[q] = a; sum += a;
        }
        float mu = brsum(sum, red) * (1.0f / 1024.0f);
        float vs = 0.f;
        #pragma unroll
        for (int q = 0; q < 4; q++) { v[q] -= mu; vs += v[q] * v[q]; }
        float var = brsum(vs, red) * (1.0f / 1024.0f);
        float rs = rsqrtf(var + EPS);
        #pragma unroll
        for (int q = 0; q < 4; q++) {
            int col = ch * 1024 + q * 256 + t;
            zr[ch][q] = v[q] * rs * ln1_g[col] + ln1_b[col];
        }
    }
    float nc[4];
    float sum = 0.f;
    #pragma unroll
    for (int q = 0; q < 4; q++) {
        int i = q * 256 + t;
        nc[q] = c[b * H_ + i] * sigm(zr[2][q] + 1.0f) + sigm(zr[0][q]) * tanhf(zr[1][q]);
        sum += nc[q];
    }
    float mu = brsum(sum, red) * (1.0f / 1024.0f);
    float vs = 0.f;
    #pragma unroll
    for (int q = 0; q < 4; q++) { nc[q] -= mu; vs += nc[q] * nc[q]; }
    float var = brsum(vs, red) * (1.0f / 1024.0f);
    float rs = rsqrtf(var + EPS);
    #pragma unroll
    for (int q = 0; q < 4; q++) {
        int i = q * 256 + t;
        float ncn = nc[q] * rs * ln2_g[i] + ln2_b[i];
        out[(size_t)b * N2 + i] = tanhf(ncn) * sigm(zr[3][q]);
        out[(size_t)b * N2 + 1024 + i] = tanhf(g_hentry[b * H_ + i]) * sigm(zr[4][q]);
    }
}

// ---------------- launch ----------------
extern "C" void kernel_launch(void* const* d_in, const int* in_sizes, int n_in,
                              void* d_out, int out_size)
{
    const float* x      = (const float*)d_in[0];
    const float* c      = (const float*)d_in[1];
    const float* hmem   = (const float*)d_in[2];
    const float* u_t    = (const float*)d_in[3];
    const float* prev   = (const float*)d_in[4];
    const float* gu     = (const float*)d_in[5];
    const float* keys   = (const float*)d_in[6];
    const float* vec_a  = (const float*)d_in[7];
    const float* fc_w   = (const float*)d_in[8];
    const float* fc_b   = (const float*)d_in[9];
    const float* W_full = (const float*)d_in[10];
    const float* bias   = (const float*)d_in[11];
    const float* W_full1= (const float*)d_in[12];
    const float* bias1  = (const float*)d_in[13];
    const float* ln1_g  = (const float*)d_in[14];
    const float* ln1_b  = (const float*)d_in[15];
    const float* ln2_g  = (const float*)d_in[16];
    const float* ln2_b  = (const float*)d_in[17];
    const float* ln3_g  = (const float*)d_in[18];
    const float* ln3_b  = (const float*)d_in[19];
    const float* ln4_g  = (const float*)d_in[20];
    const float* ln4_b  = (const float*)d_in[21];
    float* out = (float*)d_out;

    cudaFuncSetAttribute(k3_mma, cudaFuncAttributeMaxDynamicSharedMemorySize, K3_SMEM);
    cudaFuncSetAttribute(gemm_z, cudaFuncAttributeMaxDynamicSharedMemorySize, ZG_SMEM);

    // weight conversion (transpose + bf16 hi/lo split)
    wconv<<<dim3(HQ / 32, H_ / 64), dim3(32, 8)>>>(fc_w + 1600 * HQ, H_, HQ, 0);
    wconv<<<dim3(N2 / 32, XC2 / 64), dim3(32, 8)>>>(W_full1, XC2, N2, 1);
    wconv<<<dim3(N5 / 32, XC2 / 64), dim3(32, 8)>>>(W_full, XC2, N5, 2);

    // sbase GEMM (split-K=8 over 1664)
    k1a_xcu<<<B_, 128>>>(x, c, u_t);
    k1b_sgemm<<<dim3(4, 8), dim3(32, 8)>>>(fc_w);
    k1c_red<<<B_, 256>>>(fc_b);

    k2_kpart<<<M_, 256>>>(keys, fc_w);
    k3_mma<<<B_, 512, K3_SMEM>>>(hmem, vec_a);
    k4_read<<<B_, 128>>>(x, c, prev, gu, hmem, ln4_g, ln4_b);
    // g1 GEMM: [256,2560]@[2560,2048], split-K=8 (kslice 320) -> 256 blocks
    gemm_z<<<dim3(N2 / 128, B_ / 128, 8), 256, ZG_SMEM>>>(1, N2, 320);
    k6_gate<<<dim3(2, B_), 256>>>(bias1, ln3_g, ln3_b);
    // z GEMM: [256,2560]@[2560,5120], split-K=4 (kslice 640) -> 320 blocks
    gemm_z<<<dim3(N5 / 128, B_ / 128, 4), 256, ZG_SMEM>>>(2, N5, 640);
    k8_fused<<<B_, 256>>>(bias, ln1_g, ln1_b, c, ln2_g, ln2_b, out);
}

// round 13
// speedup vs baseline: 1.5160x; 1.5160x over previous
#include <cuda_runtime.h>
#include <cuda_bf16.h>
#include <cstdint>
#include <math.h>

// Shapes (fixed per problem)
#define B_   256
#define X_   512
#define H_   1024
#define M_   128
#define KK_  64
#define XH   1536      // X + H
#define XCU  1664      // X + H + M
#define XC2  2560      // X + 2H
#define HQ   256       // H/4
#define N5   5120      // 5H
#define N2   2048      // 2H
#define EPS  1e-5f

// ---------------- scratch ----------------
__device__ float g_sbase[B_ * HQ];
__device__ float g_kpart[M_ * HQ];
__device__ float g_score[B_ * M_];
__device__ float g_hentry[B_ * H_];
__device__ float g_concat[B_ * XC2];
__device__ float g_xcu[B_ * XCU];
__device__ float g_part[4 * B_ * N5];     // also covers 8*B_*N2
// bf16 hi/lo transposed weights [N, K]
__device__ __nv_bfloat16 g_Whh[HQ * H_];
__device__ __nv_bfloat16 g_Whl[HQ * H_];
__device__ __nv_bfloat16 g_W1h[N2 * XC2];
__device__ __nv_bfloat16 g_W1l[N2 * XC2];
__device__ __nv_bfloat16 g_Wfh[N5 * XC2];
__device__ __nv_bfloat16 g_Wfl[N5 * XC2];

// ---------------- low-level helpers ----------------
__device__ __forceinline__ uint32_t smem_u32(const void* p) {
    uint32_t a;
    asm("{ .reg .u64 t; cvta.to.shared.u64 t, %1; cvt.u32.u64 %0, t; }" : "=r"(a) : "l"(p));
    return a;
}
__device__ __forceinline__ void ldsm4(uint32_t* r, uint32_t a) {
    asm volatile("ldmatrix.sync.aligned.m8n8.x4.shared.b16 {%0,%1,%2,%3}, [%4];"
                 : "=r"(r[0]), "=r"(r[1]), "=r"(r[2]), "=r"(r[3]) : "r"(a));
}
__device__ __forceinline__ void mma16816(float* c, const uint32_t* a, const uint32_t* b) {
    asm volatile("mma.sync.aligned.m16n8k16.row.col.f32.bf16.bf16.f32 "
                 "{%0,%1,%2,%3}, {%4,%5,%6,%7}, {%8,%9}, {%0,%1,%2,%3};"
                 : "+f"(c[0]), "+f"(c[1]), "+f"(c[2]), "+f"(c[3])
                 : "r"(a[0]), "r"(a[1]), "r"(a[2]), "r"(a[3]), "r"(b[0]), "r"(b[1]));
}
__device__ __forceinline__ void cpa16(uint32_t dst, const void* src) {
    asm volatile("cp.async.cg.shared.global [%0], [%1], 16;" :: "r"(dst), "l"(src));
}
#define CP_COMMIT() asm volatile("cp.async.commit_group;" ::: "memory")
#define CP_WAIT1()  asm volatile("cp.async.wait_group 1;" ::: "memory")
#define CP_WAIT0()  asm volatile("cp.async.wait_group 0;" ::: "memory")

__device__ __forceinline__ uint32_t pack_hi2(float x, float y, float& lx, float& ly) {
    __nv_bfloat162 h = __floats2bfloat162_rn(x, y);
    lx = x - __bfloat162float(h.x);
    ly = y - __bfloat162float(h.y);
    return *(uint32_t*)&h;
}
__device__ __forceinline__ uint32_t pack2(float x, float y) {
    __nv_bfloat162 h = __floats2bfloat162_rn(x, y);
    return *(uint32_t*)&h;
}
__device__ __forceinline__ float sigm(float x) { return 1.0f / (1.0f + expf(-x)); }

__device__ __forceinline__ float brsum(float v, float* red) {
    int lane = threadIdx.x & 31, w = threadIdx.x >> 5;
    int nw = blockDim.x >> 5;
    #pragma unroll
    for (int o = 16; o; o >>= 1) v += __shfl_xor_sync(0xffffffffu, v, o);
    __syncthreads();
    if (lane == 0) red[w] = v;
    __syncthreads();
    float s = 0.f;
    for (int i = 0; i < nw; i++) s += red[i];
    return s;
}

// ---------------- weight transpose + bf16 hi/lo split ----------------
__global__ void wconv(const float* __restrict__ W, int K, int N, int which)
{
    __nv_bfloat16 *Whi, *Wlo;
    if (which == 0)      { Whi = g_Whh; Wlo = g_Whl; }
    else if (which == 1) { Whi = g_W1h; Wlo = g_W1l; }
    else                 { Whi = g_Wfh; Wlo = g_Wfl; }
    __shared__ float t[64][33];
    int nb = blockIdx.x * 32, kb = blockIdx.y * 64;
    int tx = threadIdx.x, ty = threadIdx.y;
    for (int r = ty; r < 64; r += 8)
        t[r][tx] = W[(size_t)(kb + r) * N + nb + tx];
    __syncthreads();
    for (int r = ty; r < 32; r += 8) {
        float v0 = t[2 * tx][r], v1 = t[2 * tx + 1][r];
        float l0, l1;
        uint32_t hp = pack_hi2(v0, v1, l0, l1);
        uint32_t lp = pack2(l0, l1);
        size_t o = (size_t)(nb + r) * K + kb + 2 * tx;
        *(uint32_t*)&Whi[o] = hp;
        *(uint32_t*)&Wlo[o] = lp;
    }
}

// ---------------- K1a: build g_xcu = [x | c | u_norm] ----------------
__global__ void k1a_xcu(const float* __restrict__ x, const float* __restrict__ c,
                        const float* __restrict__ u_t)
{
    int b = blockIdx.x, t = threadIdx.x;  // 128 threads
    __shared__ float red[4];
    float uv = u_t[b * M_ + t];
    float s = brsum(uv * uv, red);
    float inv = 1.0f / fmaxf(sqrtf(s), 1e-12f);
    float* row = g_xcu + (size_t)b * XCU;
    for (int i = t; i < X_; i += 128) row[i] = x[b * X_ + i];
    for (int i = t; i < H_; i += 128) row[X_ + i] = c[b * H_ + i];
    row[XH + t] = uv * inv;
}

// ---------------- K1b: split-K SGEMM  g_part[z] = g_xcu[:,ks] @ fc_w'[ks,:] ----------------
__global__ __launch_bounds__(256) void k1b_sgemm(const float* __restrict__ fc_w)
{
    __shared__ float As[16][64];
    __shared__ float Bs[16][256];
    int rowBase = blockIdx.x * 64;
    int kStart = blockIdx.y * 208;
    int tx = threadIdx.x, ty = threadIdx.y;
    int tid = ty * 32 + tx;

    float acc[8][8];
    #pragma unroll
    for (int i = 0; i < 8; i++)
        #pragma unroll
        for (int j = 0; j < 8; j++) acc[i][j] = 0.f;

    int am = tid >> 2;
    int ak = (tid & 3) * 4;
    int bc = (tid & 63) * 4;
    int br0 = tid >> 6;

    for (int k0 = 0; k0 < 208; k0 += 16) {
        float4 av = *(const float4*)&g_xcu[(size_t)(rowBase + am) * XCU + kStart + k0 + ak];
        As[ak + 0][am] = av.x; As[ak + 1][am] = av.y;
        As[ak + 2][am] = av.z; As[ak + 3][am] = av.w;
        #pragma unroll
        for (int r = 0; r < 4; r++) {
            int kk = r * 4 + br0;
            int krow = kStart + k0 + kk;
            int frow = (krow < XH) ? krow : krow + 1088;   // u segment -> fc_w rows 2624+
            *(float4*)&Bs[kk][bc] = *(const float4*)&fc_w[(size_t)frow * HQ + bc];
        }
        __syncthreads();
        #pragma unroll
        for (int k = 0; k < 16; k++) {
            float4 a0 = *(float4*)&As[k][ty * 8];
            float4 a1 = *(float4*)&As[k][ty * 8 + 4];
            float4 b0 = *(float4*)&Bs[k][tx * 8];
            float4 b1 = *(float4*)&Bs[k][tx * 8 + 4];
            float a[8] = {a0.x, a0.y, a0.z, a0.w, a1.x, a1.y, a1.z, a1.w};
            float b[8] = {b0.x, b0.y, b0.z, b0.w, b1.x, b1.y, b1.z, b1.w};
            #pragma unroll
            for (int i = 0; i < 8; i++)
                #pragma unroll
                for (int j = 0; j < 8; j++)
                    acc[i][j] = fmaf(a[i], b[j], acc[i][j]);
        }
        __syncthreads();
    }

    float* P = g_part + (size_t)blockIdx.y * B_ * HQ;
    #pragma unroll
    for (int i = 0; i < 8; i++) {
        int row = rowBase + ty * 8 + i;
        *(float4*)&P[(size_t)row * HQ + tx * 8]     = make_float4(acc[i][0], acc[i][1], acc[i][2], acc[i][3]);
        *(float4*)&P[(size_t)row * HQ + tx * 8 + 4] = make_float4(acc[i][4], acc[i][5], acc[i][6], acc[i][7]);
    }
}

// ---------------- K1c: reduce 8 partials + fc_b -> g_sbase ----------------
__global__ void k1c_red(const float* __restrict__ fc_b)
{
    int b = blockIdx.x, j = threadIdx.x;
    float a = fc_b[j];
    #pragma unroll
    for (int z = 0; z < 8; z++) a += g_part[((size_t)z * B_ + b) * HQ + j];
    g_sbase[b * HQ + j] = a;
}

// ================= K3: score GEMM (bf16x3) with A register-prefetch =================
// tile 128x256, BK=32, 512 threads (16 warps, 4x4), warp 32x64. stride 80 B.
#define K3_AH(b) ((b) * 10240)
#define K3_AL(b) (20480 + (b) * 10240)
#define K3_BH(b) (40960 + (b) * 20480)
#define K3_BL(b) (81920 + (b) * 20480)
#define K3_RED   122880
#define K3_SMEM  124928

__global__ __launch_bounds__(512, 1) void k3_mma(
    const float* __restrict__ hmem, const float* __restrict__ vec_a)
{
    extern __shared__ char sm[];
    uint32_t sb = smem_u32(sm);
    int tid = threadIdx.x, lane = tid & 31, wid = tid >> 5;
    int wm = wid & 3, wn = wid >> 2;   // 4 x 4 warps
    int rowBase = blockIdx.x * 128;

    float acc[2][8][4];
    #pragma unroll
    for (int i = 0; i < 2; i++)
        #pragma unroll
        for (int j = 0; j < 8; j++)
            #pragma unroll
            for (int q = 0; q < 4; q++) acc[i][j][q] = 0.f;

    int arow = tid >> 3, aq = tid & 7;           // 2 (row,q) pairs per thread (it*512)
    float4 aReg[2];
    auto ldgA = [&](int i) {
        int c0 = i * 32;
        #pragma unroll
        for (int it = 0; it < 2; it++) {
            int row = arow + it * 64;
            aReg[it] = *(const float4*)&hmem[(size_t)(rowBase + row) * H_ + c0 + aq * 4];
        }
    };
    auto stsA = [&](int buf) {
        #pragma unroll
        for (int it = 0; it < 2; it++) {
            int row = arow + it * 64;
            float4 v = aReg[it];
            float lx, ly, lz, lw;
            uint32_t h0 = pack_hi2(v.x, v.y, lx, ly);
            uint32_t h1 = pack_hi2(v.z, v.w, lz, lw);
            char* ah = sm + K3_AH(buf) + row * 80 + aq * 8;
            char* al = sm + K3_AL(buf) + row * 80 + aq * 8;
            *(uint32_t*)ah = h0; *(uint32_t*)(ah + 4) = h1;
            *(uint32_t*)al = pack2(lx, ly); *(uint32_t*)(al + 4) = pack2(lz, lw);
        }
    };
    auto loadB = [&](int i, int buf) {
        int c0 = i * 32;
        #pragma unroll
        for (int it = 0; it < 2; it++) {
            int idx = tid + it * 512;
            int row = idx >> 2, seg = idx & 3;
            cpa16(sb + K3_BH(buf) + row * 80 + seg * 16, g_Whh + (size_t)row * H_ + c0 + seg * 8);
            cpa16(sb + K3_BL(buf) + row * 80 + seg * 16, g_Whl + (size_t)row * H_ + c0 + seg * 8);
        }
    };

    const int niter = H_ / 32;   // 32
    ldgA(0); stsA(0); loadB(0, 0); CP_COMMIT();
    ldgA(1);   // prefetch next chunk into registers

    uint32_t aoffA = (uint32_t)((lane & 15) * 80 + (lane >> 4) * 16);
    uint32_t aoffB = (uint32_t)(((lane & 7) + ((lane >> 4) << 3)) * 80 + (((lane >> 3) & 1) << 4));

    for (int i = 0; i < niter; i++) {
        int buf = i & 1;
        if (i + 1 < niter) { loadB(i + 1, buf ^ 1); CP_COMMIT(); CP_WAIT1(); }
        else CP_WAIT0();
        __syncthreads();
        if (i + 1 < niter) {
            stsA(buf ^ 1);                 // store prefetched A(i+1)
            if (i + 2 < niter) ldgA(i + 2);
        }

        #pragma unroll
        for (int ks = 0; ks < 2; ks++) {
            uint32_t kso = (uint32_t)(ks * 32);
            uint32_t aH[2][4], aL[2][4], bH[8][2], bL[8][2];
            #pragma unroll
            for (int mt = 0; mt < 2; mt++) {
                uint32_t ro = (uint32_t)((wm * 32 + mt * 16) * 80) + kso;
                ldsm4(aH[mt], sb + K3_AH(buf) + ro + aoffA);
                ldsm4(aL[mt], sb + K3_AL(buf) + ro + aoffA);
            }
            #pragma unroll
            for (int p = 0; p < 4; p++) {
                uint32_t ro = (uint32_t)((wn * 64 + p * 16) * 80) + kso;
                uint32_t t4[4];
                ldsm4(t4, sb + K3_BH(buf) + ro + aoffB);
                bH[2*p][0] = t4[0]; bH[2*p][1] = t4[1]; bH[2*p+1][0] = t4[2]; bH[2*p+1][1] = t4[3];
                ldsm4(t4, sb + K3_BL(buf) + ro + aoffB);
                bL[2*p][0] = t4[0]; bL[2*p][1] = t4[1]; bL[2*p+1][0] = t4[2]; bL[2*p+1][1] = t4[3];
            }
            #pragma unroll
            for (int mt = 0; mt < 2; mt++)
                #pragma unroll
                for (int nt = 0; nt < 8; nt++) {
                    mma16816(acc[mt][nt], aH[mt], bH[nt]);
                    mma16816(acc[mt][nt], aL[mt], bH[nt]);
                    mma16816(acc[mt][nt], aH[mt], bL[nt]);
                }
        }
        __syncthreads();
    }

    // epilogue: + sbase + kpart, tanh, dot vec_a, reduce over 256 cols
    float* sred = (float*)(sm + K3_RED);   // [128][4]
    int bi = rowBase >> 7;
    const float* sb_row = g_sbase + bi * HQ;
    #pragma unroll
    for (int mt = 0; mt < 2; mt++) {
        #pragma unroll
        for (int h = 0; h < 2; h++) {
            int rl = wm * 32 + mt * 16 + (lane >> 2) + h * 8;  // 0..127 = m index
            const float* kp_row = g_kpart + rl * HQ;
            float rsum = 0.f;
            #pragma unroll
            for (int nt = 0; nt < 8; nt++) {
                #pragma unroll
                for (int j = 0; j < 2; j++) {
                    int col = wn * 64 + nt * 8 + (lane & 3) * 2 + j;
                    float v = acc[mt][nt][h * 2 + j] + sb_row[col] + kp_row[col];
                    rsum = fmaf(tanhf(v), vec_a[col], rsum);
                }
            }
            rsum += __shfl_xor_sync(0xffffffffu, rsum, 1);
            rsum += __shfl_xor_sync(0xffffffffu, rsum, 2);
            if ((lane & 3) == 0) sred[rl * 4 + wn] = rsum;
        }
    }
    __syncthreads();
    if (tid < 128)
        g_score[rowBase + tid] = sred[tid * 4] + sred[tid * 4 + 1]
                               + sred[tid * 4 + 2] + sred[tid * 4 + 3];
}

// ================= z GEMMs: bf16x3 with A register-prefetch =================
#define ZG_AH(b) ((b) * 10240)
#define ZG_AL(b) (20480 + (b) * 10240)
#define ZG_BH(b) (40960 + (b) * 10240)
#define ZG_BL(b) (61440 + (b) * 10240)
#define ZG_SMEM  81920

__global__ __launch_bounds__(256, 2) void gemm_z(int which, int Nfull, int kslice)
{
    extern __shared__ char sm[];
    uint32_t sb = smem_u32(sm);
    const __nv_bfloat16 *Bh, *Bl;
    if (which == 1) { Bh = g_W1h; Bl = g_W1l; }
    else            { Bh = g_Wfh; Bl = g_Wfl; }
    int tid = threadIdx.x, lane = tid & 31, wid = tid >> 5;
    int wm = wid & 3, wn = wid >> 2;
    int rowBase = blockIdx.y * 128;
    int colBase = blockIdx.x * 128;
    int kStart  = blockIdx.z * kslice;

    float acc[2][8][4];
    #pragma unroll
    for (int i = 0; i < 2; i++)
        #pragma unroll
        for (int j = 0; j < 8; j++)
            #pragma unroll
            for (int q = 0; q < 4; q++) acc[i][j][q] = 0.f;

    int arow = tid >> 3, aq = tid & 7;
    float4 aReg[4];
    auto ldgA = [&](int i) {
        int c0 = kStart + i * 32;
        #pragma unroll
        for (int it = 0; it < 4; it++) {
            int row = arow + it * 32;
            aReg[it] = *(const float4*)&g_concat[(size_t)(rowBase + row) * XC2 + c0 + aq * 4];
        }
    };
    auto stsA = [&](int buf) {
        #pragma unroll
        for (int it = 0; it < 4; it++) {
            int row = arow + it * 32;
            float4 v = aReg[it];
            float lx, ly, lz, lw;
            uint32_t h0 = pack_hi2(v.x, v.y, lx, ly);
            uint32_t h1 = pack_hi2(v.z, v.w, lz, lw);
            char* ah = sm + ZG_AH(buf) + row * 80 + aq * 8;
            char* al = sm + ZG_AL(buf) + row * 80 + aq * 8;
            *(uint32_t*)ah = h0; *(uint32_t*)(ah + 4) = h1;
            *(uint32_t*)al = pack2(lx, ly); *(uint32_t*)(al + 4) = pack2(lz, lw);
        }
    };
    auto loadB = [&](int i, int buf) {
        int c0 = kStart + i * 32;
        #pragma unroll
        for (int it = 0; it < 2; it++) {
            int idx = tid + it * 256;
            int row = idx >> 2, seg = idx & 3;
            cpa16(sb + ZG_BH(buf) + row * 80 + seg * 16, Bh + (size_t)(colBase + row) * XC2 + c0 + seg * 8);
            cpa16(sb + ZG_BL(buf) + row * 80 + seg * 16, Bl + (size_t)(colBase + row) * XC2 + c0 + seg * 8);
        }
    };

    const int niter = kslice / 32;
    ldgA(0); stsA(0); loadB(0, 0); CP_COMMIT();
    ldgA(1);

    uint32_t aoffA = (uint32_t)((lane & 15) * 80 + (lane >> 4) * 16);
    uint32_t aoffB = (uint32_t)(((lane & 7) + ((lane >> 4) << 3)) * 80 + (((lane >> 3) & 1) << 4));

    for (int i = 0; i < niter; i++) {
        int buf = i & 1;
        if (i + 1 < niter) { loadB(i + 1, buf ^ 1); CP_COMMIT(); CP_WAIT1(); }
        else CP_WAIT0();
        __syncthreads();
        if (i + 1 < niter) {
            stsA(buf ^ 1);
            if (i + 2 < niter) ldgA(i + 2);
        }

        #pragma unroll
        for (int ks = 0; ks < 2; ks++) {
            uint32_t kso = (uint32_t)(ks * 32);
            uint32_t aH[2][4], aL[2][4], bH[8][2], bL[8][2];
            #pragma unroll
            for (int mt = 0; mt < 2; mt++) {
                uint32_t ro = (uint32_t)((wm * 32 + mt * 16) * 80) + kso;
                ldsm4(aH[mt], sb + ZG_AH(buf) + ro + aoffA);
                ldsm4(aL[mt], sb + ZG_AL(buf) + ro + aoffA);
            }
            #pragma unroll
            for (int p = 0; p < 4; p++) {
                uint32_t ro = (uint32_t)((wn * 64 + p * 16) * 80) + kso;
                uint32_t t4[4];
                ldsm4(t4, sb + ZG_BH(buf) + ro + aoffB);
                bH[2*p][0] = t4[0]; bH[2*p][1] = t4[1]; bH[2*p+1][0] = t4[2]; bH[2*p+1][1] = t4[3];
                ldsm4(t4, sb + ZG_BL(buf) + ro + aoffB);
                bL[2*p][0] = t4[0]; bL[2*p][1] = t4[1]; bL[2*p+1][0] = t4[2]; bL[2*p+1][1] = t4[3];
            }
            #pragma unroll
            for (int mt = 0; mt < 2; mt++)
                #pragma unroll
                for (int nt = 0; nt < 8; nt++) {
                    mma16816(acc[mt][nt], aH[mt], bH[nt]);
                    mma16816(acc[mt][nt], aL[mt], bH[nt]);
                    mma16816(acc[mt][nt], aH[mt], bL[nt]);
                }
        }
        __syncthreads();
    }

    float* P = g_part + (size_t)blockIdx.z * B_ * Nfull;
    int row0 = rowBase + wm * 32;
    int col0 = colBase + wn * 64;
    #pragma unroll
    for (int mt = 0; mt < 2; mt++)
        #pragma unroll
        for (int nt = 0; nt < 8; nt++)
            #pragma unroll
            for (int h = 0; h < 2; h++) {
                int r = row0 + mt * 16 + (lane >> 2) + h * 8;
                int cc = col0 + nt * 8 + (lane & 3) * 2;
                *(float2*)&P[(size_t)r * Nfull + cc] =
                    make_float2(acc[mt][nt][h * 2], acc[mt][nt][h * 2 + 1]);
            }
}

// ---------------- K2: k_part ----------------
__global__ void k2_kpart(const float* __restrict__ keys, const float* __restrict__ fc_w)
{
    __shared__ float ks[KK_];
    int m = blockIdx.x, j = threadIdx.x;
    if (j < KK_) ks[j] = keys[m * KK_ + j];
    __syncthreads();
    float acc = 0.f;
    #pragma unroll 8
    for (int i = 0; i < KK_; i++) acc = fmaf(ks[i], fc_w[(XH + i) * HQ + j], acc);
    g_kpart[m * HQ + j] = acc;
}

// ---------------- K4: score LN + gumbel argmax + gather ----------------
__global__ void k4_read(
    const float* __restrict__ x, const float* __restrict__ c,
    const float* __restrict__ prev, const float* __restrict__ gu,
    const float* __restrict__ hmem,
    const float* __restrict__ ln4_g, const float* __restrict__ ln4_b)
{
    int b = blockIdx.x, t = threadIdx.x;
    __shared__ float red[4];
    __shared__ float redf[4];
    __shared__ int   redi[4];
    __shared__ float s_vmax;
    __shared__ int   s_arg;

    float s = g_score[b * M_ + t] - prev[b * M_ + t] * 100.0f;
    float mu = brsum(s, red) * (1.0f / 128.0f);
    float d = s - mu;
    float var = brsum(d * d, red) * (1.0f / 128.0f);
    float sn = d * rsqrtf(var + EPS) * ln4_g[t] + ln4_b[t];
    float u = gu[b * M_ + t];
    float gmb = -logf(1e-20f - logf(1e-20f + u));
    float v = sn + gmb;

    float bv = v; int bidx = t;
    #pragma unroll
    for (int o = 16; o; o >>= 1) {
        float ov = __shfl_xor_sync(0xffffffffu, bv, o);
        int   oi = __shfl_xor_sync(0xffffffffu, bidx, o);
        if (ov > bv || (ov == bv && oi < bidx)) { bv = ov; bidx = oi; }
    }
    __syncthreads();
    if ((t & 31) == 0) { redf[t >> 5] = bv; redi[t >> 5] = bidx; }
    __syncthreads();
    if (t == 0) {
        float fv = redf[0]; int fi = redi[0];
        for (int w = 1; w < 4; w++)
            if (redf[w] > fv || (redf[w] == fv && redi[w] < fi)) { fv = redf[w]; fi = redi[w]; }
        s_vmax = fv; s_arg = fi;
    }
    __syncthreads();
    float e = expf(v - s_vmax);
    float ssum = brsum(e, red);
    float ymax = 1.0f / ssum;
    float w = (1.0f - ymax) + ymax;
    int mi = s_arg;

    const float* hrow = hmem + ((size_t)b * M_ + mi) * H_;
    for (int i = t; i < H_; i += 128) {
        float hv = w * hrow[i];
        g_hentry[b * H_ + i] = hv;
        g_concat[b * XC2 + XH + i] = hv;
        g_concat[b * XC2 + X_ + i] = c[b * H_ + i];
    }
    for (int i = t; i < X_; i += 128) g_concat[b * XC2 + i] = x[b * X_ + i];
}

// ---------------- K6: reduce split-K(8) + bias1 + chunk-LN + sigmoid gate ----------------
__global__ void k6_gate(
    const float* __restrict__ bias1,
    const float* __restrict__ ln3_g, const float* __restrict__ ln3_b)
{
    int ch = blockIdx.x, b = blockIdx.y;
    int t = threadIdx.x;
    __shared__ float red[8];
    float v[4];
    float sum = 0.f;
    #pragma unroll
    for (int q = 0; q < 4; q++) {
        int col = ch * 1024 + q * 256 + t;
        float a = 0.f;
        #pragma unroll
        for (int z = 0; z < 8; z++) a += g_part[((size_t)z * B_ + b) * N2 + col];
        a += bias1[col];
        v[q] = a; sum += a;
    }
    float mu = brsum(sum, red) * (1.0f / 1024.0f);
    float vs = 0.f;
    #pragma unroll
    for (int q = 0; q < 4; q++) { v[q] -= mu; vs += v[q] * v[q]; }
    float var = brsum(vs, red) * (1.0f / 1024.0f);
    float rs = rsqrtf(var + EPS);
    #pragma unroll
    for (int q = 0; q < 4; q++) {
        int col = ch * 1024 + q * 256 + t;
        float g1 = sigm(v[q] * rs * ln3_g[col] + ln3_b[col]);
        g_concat[b * XC2 + X_ + col] *= g1;
    }
}

// ---------------- K8 fused: reduce split-K(4) + bias + chunk-LN(5) + cell + LN + outputs ----
__global__ void k8_fused(
    const float* __restrict__ bias,
    const float* __restrict__ ln1_g, const float* __restrict__ ln1_b,
    const float* __restrict__ c,
    const float* __restrict__ ln2_g, const float* __restrict__ ln2_b,
    float* __restrict__ out)
{
    int b = blockIdx.x, t = threadIdx.x;   // 256 threads
    __shared__ float red[8];
    float zr[5][4];
    #pragma unroll
    for (int ch = 0; ch < 5; ch++) {
        float v[4];
        float sum = 0.f;
        #pragma unroll
        for (int q = 0; q < 4; q++) {
            int col = ch * 1024 + q * 256 + t;
            float a = 0.f;
            #pragma unroll
            for (int z = 0; z < 4; z++) a += g_part[((size_t)z * B_ + b) * N5 + col];
            a += bias[col];
            v[q] = a; sum += a;
        }
        float mu = brsum(sum, red) * (1.0f / 1024.0f);
        float vs = 0.f;
        #pragma unroll
        for (int q = 0; q < 4; q++) { v[q] -= mu; vs += v[q] * v[q]; }
        float var = brsum(vs, red) * (1.0f / 1024.0f);
        float rs = rsqrtf(var + EPS);
        #pragma unroll
        for (int q = 0; q < 4; q++) {
            int col = ch * 1024 + q * 256 + t;
            zr[ch][q] = v[q] * rs * ln1_g[col] + ln1_b[col];
        }
    }
    float nc[4];
    float sum = 0.f;
    #pragma unroll
    for (int q = 0; q < 4; q++) {
        int i = q * 256 + t;
        nc[q] = c[b * H_ + i] * sigm(zr[2][q] + 1.0f) + sigm(zr[0][q]) * tanhf(zr[1][q]);
        sum += nc[q];
    }
    float mu = brsum(sum, red) * (1.0f / 1024.0f);
    float vs = 0.f;
    #pragma unroll
    for (int q = 0; q < 4; q++) { nc[q] -= mu; vs += nc[q] * nc[q]; }
    float var = brsum(vs, red) * (1.0f / 1024.0f);
    float rs = rsqrtf(var + EPS);
    #pragma unroll
    for (int q = 0; q < 4; q++) {
        int i = q * 256 + t;
        float ncn = nc[q] * rs * ln2_g[i] + ln2_b[i];
        out[(size_t)b * N2 + i] = tanhf(ncn) * sigm(zr[3][q]);
        out[(size_t)b * N2 + 1024 + i] = tanhf(g_hentry[b * H_ + i]) * sigm(zr[4][q]);
    }
}

// ---------------- launch ----------------
extern "C" void kernel_launch(void* const* d_in, const int* in_sizes, int n_in,
                              void* d_out, int out_size)
{
    const float* x      = (const float*)d_in[0];
    const float* c      = (const float*)d_in[1];
    const float* hmem   = (const float*)d_in[2];
    const float* u_t    = (const float*)d_in[3];
    const float* prev   = (const float*)d_in[4];
    const float* gu     = (const float*)d_in[5];
    const float* keys   = (const float*)d_in[6];
    const float* vec_a  = (const float*)d_in[7];
    const float* fc_w   = (const float*)d_in[8];
    const float* fc_b   = (const float*)d_in[9];
    const float* W_full = (const float*)d_in[10];
    const float* bias   = (const float*)d_in[11];
    const float* W_full1= (const float*)d_in[12];
    const float* bias1  = (const float*)d_in[13];
    const float* ln1_g  = (const float*)d_in[14];
    const float* ln1_b  = (const float*)d_in[15];
    const float* ln2_g  = (const float*)d_in[16];
    const float* ln2_b  = (const float*)d_in[17];
    const float* ln3_g  = (const float*)d_in[18];
    const float* ln3_b  = (const float*)d_in[19];
    const float* ln4_g  = (const float*)d_in[20];
    const float* ln4_b  = (const float*)d_in[21];
    float* out = (float*)d_out;

    cudaFuncSetAttribute(k3_mma, cudaFuncAttributeMaxDynamicSharedMemorySize, K3_SMEM);
    cudaFuncSetAttribute(gemm_z, cudaFuncAttributeMaxDynamicSharedMemorySize, ZG_SMEM);

    // weight conversion (transpose + bf16 hi/lo split)
    wconv<<<dim3(HQ / 32, H_ / 64), dim3(32, 8)>>>(fc_w + 1600 * HQ, H_, HQ, 0);
    wconv<<<dim3(N2 / 32, XC2 / 64), dim3(32, 8)>>>(W_full1, XC2, N2, 1);
    wconv<<<dim3(N5 / 32, XC2 / 64), dim3(32, 8)>>>(W_full, XC2, N5, 2);

    // sbase GEMM (split-K=8 over 1664)
    k1a_xcu<<<B_, 128>>>(x, c, u_t);
    k1b_sgemm<<<dim3(4, 8), dim3(32, 8)>>>(fc_w);
    k1c_red<<<B_, 256>>>(fc_b);

    k2_kpart<<<M_, 256>>>(keys, fc_w);
    k3_mma<<<B_, 512, K3_SMEM>>>(hmem, vec_a);
    k4_read<<<B_, 128>>>(x, c, prev, gu, hmem, ln4_g, ln4_b);
    // g1 GEMM: [256,2560]@[2560,2048], split-K=8 (kslice 320) -> 256 blocks
    gemm_z<<<dim3(N2 / 128, B_ / 128, 8), 256, ZG_SMEM>>>(1, N2, 320);
    k6_gate<<<dim3(2, B_), 256>>>(bias1, ln3_g, ln3_b);
    // z GEMM: [256,2560]@[2560,5120], split-K=4 (kslice 640) -> 320 blocks
    gemm_z<<<dim3(N5 / 128, B_ / 128, 4), 256, ZG_SMEM>>>(2, N5, 640);
    k8_fused<<<B_, 256>>>(bias, ln1_g, ln1_b, c, ln2_g, ln2_b, out);
}

// round 16
// speedup vs baseline: 1.5329x; 1.0112x over previous
#include <cuda_runtime.h>
#include <cuda_bf16.h>
#include <cstdint>
#include <math.h>

// Shapes (fixed per problem)
#define B_   256
#define X_   512
#define H_   1024
#define M_   128
#define KK_  64
#define XH   1536      // X + H
#define XCU  1664      // X + H + M
#define XC2  2560      // X + 2H
#define HQ   256       // H/4
#define N5   5120      // 5H
#define N2   2048      // 2H
#define EPS  1e-5f

// ---------------- scratch ----------------
__device__ float g_sbase[B_ * HQ];
__device__ float g_kpart[M_ * HQ];
__device__ float g_score[B_ * M_];
__device__ float g_hentry[B_ * H_];
__device__ float g_concat[B_ * XC2];
__device__ float g_xcu[B_ * XCU];
__device__ float g_part[4 * B_ * N5];     // also covers 8*B_*N2
// bf16 hi/lo transposed weights [N, K]
__device__ __nv_bfloat16 g_Whh[HQ * H_];
__device__ __nv_bfloat16 g_Whl[HQ * H_];
__device__ __nv_bfloat16 g_W1h[N2 * XC2];
__device__ __nv_bfloat16 g_W1l[N2 * XC2];
__device__ __nv_bfloat16 g_Wfh[N5 * XC2];
__device__ __nv_bfloat16 g_Wfl[N5 * XC2];

// ---------------- low-level helpers ----------------
__device__ __forceinline__ uint32_t smem_u32(const void* p) {
    uint32_t a;
    asm("{ .reg .u64 t; cvta.to.shared.u64 t, %1; cvt.u32.u64 %0, t; }" : "=r"(a) : "l"(p));
    return a;
}
__device__ __forceinline__ void ldsm4(uint32_t* r, uint32_t a) {
    asm volatile("ldmatrix.sync.aligned.m8n8.x4.shared.b16 {%0,%1,%2,%3}, [%4];"
                 : "=r"(r[0]), "=r"(r[1]), "=r"(r[2]), "=r"(r[3]) : "r"(a));
}
__device__ __forceinline__ void mma16816(float* c, const uint32_t* a, const uint32_t* b) {
    asm volatile("mma.sync.aligned.m16n8k16.row.col.f32.bf16.bf16.f32 "
                 "{%0,%1,%2,%3}, {%4,%5,%6,%7}, {%8,%9}, {%0,%1,%2,%3};"
                 : "+f"(c[0]), "+f"(c[1]), "+f"(c[2]), "+f"(c[3])
                 : "r"(a[0]), "r"(a[1]), "r"(a[2]), "r"(a[3]), "r"(b[0]), "r"(b[1]));
}
__device__ __forceinline__ void cpa16(uint32_t dst, const void* src) {
    asm volatile("cp.async.cg.shared.global [%0], [%1], 16;" :: "r"(dst), "l"(src));
}
#define CP_COMMIT() asm volatile("cp.async.commit_group;" ::: "memory")
#define CP_WAIT2()  asm volatile("cp.async.wait_group 2;" ::: "memory")
#define CP_WAIT1()  asm volatile("cp.async.wait_group 1;" ::: "memory")
#define CP_WAIT0()  asm volatile("cp.async.wait_group 0;" ::: "memory")

__device__ __forceinline__ uint32_t pack_hi2(float x, float y, float& lx, float& ly) {
    __nv_bfloat162 h = __floats2bfloat162_rn(x, y);
    lx = x - __bfloat162float(h.x);
    ly = y - __bfloat162float(h.y);
    return *(uint32_t*)&h;
}
__device__ __forceinline__ uint32_t pack2(float x, float y) {
    __nv_bfloat162 h = __floats2bfloat162_rn(x, y);
    return *(uint32_t*)&h;
}
__device__ __forceinline__ float sigm(float x) { return 1.0f / (1.0f + expf(-x)); }

__device__ __forceinline__ float brsum(float v, float* red) {
    int lane = threadIdx.x & 31, w = threadIdx.x >> 5;
    int nw = blockDim.x >> 5;
    #pragma unroll
    for (int o = 16; o; o >>= 1) v += __shfl_xor_sync(0xffffffffu, v, o);
    __syncthreads();
    if (lane == 0) red[w] = v;
    __syncthreads();
    float s = 0.f;
    for (int i = 0; i < nw; i++) s += red[i];
    return s;
}

// ---------------- weight transpose + bf16 hi/lo split ----------------
__global__ void wconv(const float* __restrict__ W, int K, int N, int which)
{
    __nv_bfloat16 *Whi, *Wlo;
    if (which == 0)      { Whi = g_Whh; Wlo = g_Whl; }
    else if (which == 1) { Whi = g_W1h; Wlo = g_W1l; }
    else                 { Whi = g_Wfh; Wlo = g_Wfl; }
    __shared__ float t[64][33];
    int nb = blockIdx.x * 32, kb = blockIdx.y * 64;
    int tx = threadIdx.x, ty = threadIdx.y;
    for (int r = ty; r < 64; r += 8)
        t[r][tx] = W[(size_t)(kb + r) * N + nb + tx];
    __syncthreads();
    for (int r = ty; r < 32; r += 8) {
        float v0 = t[2 * tx][r], v1 = t[2 * tx + 1][r];
        float l0, l1;
        uint32_t hp = pack_hi2(v0, v1, l0, l1);
        uint32_t lp = pack2(l0, l1);
        size_t o = (size_t)(nb + r) * K + kb + 2 * tx;
        *(uint32_t*)&Whi[o] = hp;
        *(uint32_t*)&Wlo[o] = lp;
    }
}

// ---------------- K1a: build g_xcu = [x | c | u_norm] ----------------
__global__ void k1a_xcu(const float* __restrict__ x, const float* __restrict__ c,
                        const float* __restrict__ u_t)
{
    int b = blockIdx.x, t = threadIdx.x;  // 128 threads
    __shared__ float red[4];
    float uv = u_t[b * M_ + t];
    float s = brsum(uv * uv, red);
    float inv = 1.0f / fmaxf(sqrtf(s), 1e-12f);
    float* row = g_xcu + (size_t)b * XCU;
    for (int i = t; i < X_; i += 128) row[i] = x[b * X_ + i];
    for (int i = t; i < H_; i += 128) row[X_ + i] = c[b * H_ + i];
    row[XH + t] = uv * inv;
}

// ---------------- K1b: split-K SGEMM  g_part[z] = g_xcu[:,ks] @ fc_w'[ks,:] ----------------
__global__ __launch_bounds__(256) void k1b_sgemm(const float* __restrict__ fc_w)
{
    __shared__ float As[16][64];
    __shared__ float Bs[16][256];
    int rowBase = blockIdx.x * 64;
    int kStart = blockIdx.y * 208;
    int tx = threadIdx.x, ty = threadIdx.y;
    int tid = ty * 32 + tx;

    float acc[8][8];
    #pragma unroll
    for (int i = 0; i < 8; i++)
        #pragma unroll
        for (int j = 0; j < 8; j++) acc[i][j] = 0.f;

    int am = tid >> 2;
    int ak = (tid & 3) * 4;
    int bc = (tid & 63) * 4;
    int br0 = tid >> 6;

    for (int k0 = 0; k0 < 208; k0 += 16) {
        float4 av = *(const float4*)&g_xcu[(size_t)(rowBase + am) * XCU + kStart + k0 + ak];
        As[ak + 0][am] = av.x; As[ak + 1][am] = av.y;
        As[ak + 2][am] = av.z; As[ak + 3][am] = av.w;
        #pragma unroll
        for (int r = 0; r < 4; r++) {
            int kk = r * 4 + br0;
            int krow = kStart + k0 + kk;
            int frow = (krow < XH) ? krow : krow + 1088;   // u segment -> fc_w rows 2624+
            *(float4*)&Bs[kk][bc] = *(const float4*)&fc_w[(size_t)frow * HQ + bc];
        }
        __syncthreads();
        #pragma unroll
        for (int k = 0; k < 16; k++) {
            float4 a0 = *(float4*)&As[k][ty * 8];
            float4 a1 = *(float4*)&As[k][ty * 8 + 4];
            float4 b0 = *(float4*)&Bs[k][tx * 8];
            float4 b1 = *(float4*)&Bs[k][tx * 8 + 4];
            float a[8] = {a0.x, a0.y, a0.z, a0.w, a1.x, a1.y, a1.z, a1.w};
            float b[8] = {b0.x, b0.y, b0.z, b0.w, b1.x, b1.y, b1.z, b1.w};
            #pragma unroll
            for (int i = 0; i < 8; i++)
                #pragma unroll
                for (int j = 0; j < 8; j++)
                    acc[i][j] = fmaf(a[i], b[j], acc[i][j]);
        }
        __syncthreads();
    }

    float* P = g_part + (size_t)blockIdx.y * B_ * HQ;
    #pragma unroll
    for (int i = 0; i < 8; i++) {
        int row = rowBase + ty * 8 + i;
        *(float4*)&P[(size_t)row * HQ + tx * 8]     = make_float4(acc[i][0], acc[i][1], acc[i][2], acc[i][3]);
        *(float4*)&P[(size_t)row * HQ + tx * 8 + 4] = make_float4(acc[i][4], acc[i][5], acc[i][6], acc[i][7]);
    }
}

// ---------------- K1c: reduce 8 partials + fc_b -> g_sbase ----------------
__global__ void k1c_red(const float* __restrict__ fc_b)
{
    int b = blockIdx.x, j = threadIdx.x;
    float a = fc_b[j];
    #pragma unroll
    for (int z = 0; z < 8; z++) a += g_part[((size_t)z * B_ + b) * HQ + j];
    g_sbase[b * HQ + j] = a;
}

// ================= K3: score GEMM (bf16x3), A reg-prefetch + 3-stage B =================
// tile 128x256, BK=32, 512 threads (16 warps, 4x4), warp 32x64. stride 80 B.
#define K3_AH(b) ((b) * 10240)
#define K3_AL(b) (20480 + (b) * 10240)
#define K3_BH(b) (40960 + (b) * 40960)
#define K3_BL(b) (61440 + (b) * 40960)
#define K3_RED   163840
#define K3_SMEM  165888

__global__ __launch_bounds__(512, 1) void k3_mma(
    const float* __restrict__ hmem, const float* __restrict__ vec_a)
{
    extern __shared__ char sm[];
    uint32_t sb = smem_u32(sm);
    int tid = threadIdx.x, lane = tid & 31, wid = tid >> 5;
    int wm = wid & 3, wn = wid >> 2;   // 4 x 4 warps
    int rowBase = blockIdx.x * 128;

    float acc[2][8][4];
    #pragma unroll
    for (int i = 0; i < 2; i++)
        #pragma unroll
        for (int j = 0; j < 8; j++)
            #pragma unroll
            for (int q = 0; q < 4; q++) acc[i][j][q] = 0.f;

    int arow = tid >> 3, aq = tid & 7;
    float4 aReg[2];
    auto ldgA = [&](int i) {
        int c0 = i * 32;
        #pragma unroll
        for (int it = 0; it < 2; it++) {
            int row = arow + it * 64;
            aReg[it] = *(const float4*)&hmem[(size_t)(rowBase + row) * H_ + c0 + aq * 4];
        }
    };
    auto stsA = [&](int buf) {
        #pragma unroll
        for (int it = 0; it < 2; it++) {
            int row = arow + it * 64;
            float4 v = aReg[it];
            float lx, ly, lz, lw;
            uint32_t h0 = pack_hi2(v.x, v.y, lx, ly);
            uint32_t h1 = pack_hi2(v.z, v.w, lz, lw);
            char* ah = sm + K3_AH(buf) + row * 80 + aq * 8;
            char* al = sm + K3_AL(buf) + row * 80 + aq * 8;
            *(uint32_t*)ah = h0; *(uint32_t*)(ah + 4) = h1;
            *(uint32_t*)al = pack2(lx, ly); *(uint32_t*)(al + 4) = pack2(lz, lw);
        }
    };
    auto loadB = [&](int i, int buf) {
        int c0 = i * 32;
        #pragma unroll
        for (int it = 0; it < 2; it++) {
            int idx = tid + it * 512;
            int row = idx >> 2, seg = idx & 3;
            cpa16(sb + K3_BH(buf) + row * 80 + seg * 16, g_Whh + (size_t)row * H_ + c0 + seg * 8);
            cpa16(sb + K3_BL(buf) + row * 80 + seg * 16, g_Whl + (size_t)row * H_ + c0 + seg * 8);
        }
    };

    const int niter = H_ / 32;   // 32
    ldgA(0); stsA(0);
    loadB(0, 0); CP_COMMIT();
    loadB(1, 1); CP_COMMIT();
    ldgA(1);   // prefetch next A chunk into registers

    uint32_t aoffA = (uint32_t)((lane & 15) * 80 + (lane >> 4) * 16);
    uint32_t aoffB = (uint32_t)(((lane & 7) + ((lane >> 4) << 3)) * 80 + (((lane >> 3) & 1) << 4));

    for (int i = 0; i < niter; i++) {
        int buf = i % 3;       // B buffer
        int abuf = i & 1;      // A buffer
        if (i + 2 < niter)      { loadB(i + 2, (i + 2) % 3); CP_COMMIT(); CP_WAIT2(); }
        else if (i + 1 < niter) { CP_WAIT1(); }
        else                    { CP_WAIT0(); }
        __syncthreads();
        if (i + 1 < niter) {
            stsA(abuf ^ 1);
            if (i + 2 < niter) ldgA(i + 2);
        }

        #pragma unroll
        for (int ks = 0; ks < 2; ks++) {
            uint32_t kso = (uint32_t)(ks * 32);
            uint32_t aH[2][4], aL[2][4], bH[8][2], bL[8][2];
            #pragma unroll
            for (int mt = 0; mt < 2; mt++) {
                uint32_t ro = (uint32_t)((wm * 32 + mt * 16) * 80) + kso;
                ldsm4(aH[mt], sb + K3_AH(abuf) + ro + aoffA);
                ldsm4(aL[mt], sb + K3_AL(abuf) + ro + aoffA);
            }
            #pragma unroll
            for (int p = 0; p < 4; p++) {
                uint32_t ro = (uint32_t)((wn * 64 + p * 16) * 80) + kso;
                uint32_t t4[4];
                ldsm4(t4, sb + K3_BH(buf) + ro + aoffB);
                bH[2*p][0] = t4[0]; bH[2*p][1] = t4[1]; bH[2*p+1][0] = t4[2]; bH[2*p+1][1] = t4[3];
                ldsm4(t4, sb + K3_BL(buf) + ro + aoffB);
                bL[2*p][0] = t4[0]; bL[2*p][1] = t4[1]; bL[2*p+1][0] = t4[2]; bL[2*p+1][1] = t4[3];
            }
            #pragma unroll
            for (int mt = 0; mt < 2; mt++)
                #pragma unroll
                for (int nt = 0; nt < 8; nt++) {
                    mma16816(acc[mt][nt], aH[mt], bH[nt]);
                    mma16816(acc[mt][nt], aL[mt], bH[nt]);
                    mma16816(acc[mt][nt], aH[mt], bL[nt]);
                }
        }
        __syncthreads();
    }

    // epilogue: + sbase + kpart, tanh, dot vec_a, reduce over 256 cols
    float* sred = (float*)(sm + K3_RED);   // [128][4]
    int bi = rowBase >> 7;
    const float* sb_row = g_sbase + bi * HQ;
    #pragma unroll
    for (int mt = 0; mt < 2; mt++) {
        #pragma unroll
        for (int h = 0; h < 2; h++) {
            int rl = wm * 32 + mt * 16 + (lane >> 2) + h * 8;  // 0..127 = m index
            const float* kp_row = g_kpart + rl * HQ;
            float rsum = 0.f;
            #pragma unroll
            for (int nt = 0; nt < 8; nt++) {
                #pragma unroll
                for (int j = 0; j < 2; j++) {
                    int col = wn * 64 + nt * 8 + (lane & 3) * 2 + j;
                    float v = acc[mt][nt][h * 2 + j] + sb_row[col] + kp_row[col];
                    rsum = fmaf(tanhf(v), vec_a[col], rsum);
                }
            }
            rsum += __shfl_xor_sync(0xffffffffu, rsum, 1);
            rsum += __shfl_xor_sync(0xffffffffu, rsum, 2);
            if ((lane & 3) == 0) sred[rl * 4 + wn] = rsum;
        }
    }
    __syncthreads();
    if (tid < 128)
        g_score[rowBase + tid] = sred[tid * 4] + sred[tid * 4 + 1]
                               + sred[tid * 4 + 2] + sred[tid * 4 + 3];
}

// ================= z GEMMs: bf16x3, A reg-prefetch + 3-stage B =================
#define ZG_AH(b) ((b) * 10240)
#define ZG_AL(b) (20480 + (b) * 10240)
#define ZG_BH(b) (40960 + (b) * 20480)
#define ZG_BL(b) (51200 + (b) * 20480)
#define ZG_SMEM  102400

__global__ __launch_bounds__(256, 2) void gemm_z(int which, int Nfull, int kslice)
{
    extern __shared__ char sm[];
    uint32_t sb = smem_u32(sm);
    const __nv_bfloat16 *Bh, *Bl;
    if (which == 1) { Bh = g_W1h; Bl = g_W1l; }
    else            { Bh = g_Wfh; Bl = g_Wfl; }
    int tid = threadIdx.x, lane = tid & 31, wid = tid >> 5;
    int wm = wid & 3, wn = wid >> 2;
    int rowBase = blockIdx.y * 128;
    int colBase = blockIdx.x * 128;
    int kStart  = blockIdx.z * kslice;

    float acc[2][8][4];
    #pragma unroll
    for (int i = 0; i < 2; i++)
        #pragma unroll
        for (int j = 0; j < 8; j++)
            #pragma unroll
            for (int q = 0; q < 4; q++) acc[i][j][q] = 0.f;

    int arow = tid >> 3, aq = tid & 7;
    float4 aReg[4];
    auto ldgA = [&](int i) {
        int c0 = kStart + i * 32;
        #pragma unroll
        for (int it = 0; it < 4; it++) {
            int row = arow + it * 32;
            aReg[it] = *(const float4*)&g_concat[(size_t)(rowBase + row) * XC2 + c0 + aq * 4];
        }
    };
    auto stsA = [&](int buf) {
        #pragma unroll
        for (int it = 0; it < 4; it++) {
            int row = arow + it * 32;
            float4 v = aReg[it];
            float lx, ly, lz, lw;
            uint32_t h0 = pack_hi2(v.x, v.y, lx, ly);
            uint32_t h1 = pack_hi2(v.z, v.w, lz, lw);
            char* ah = sm + ZG_AH(buf) + row * 80 + aq * 8;
            char* al = sm + ZG_AL(buf) + row * 80 + aq * 8;
            *(uint32_t*)ah = h0; *(uint32_t*)(ah + 4) = h1;
            *(uint32_t*)al = pack2(lx, ly); *(uint32_t*)(al + 4) = pack2(lz, lw);
        }
    };
    auto loadB = [&](int i, int buf) {
        int c0 = kStart + i * 32;
        #pragma unroll
        for (int it = 0; it < 2; it++) {
            int idx = tid + it * 256;
            int row = idx >> 2, seg = idx & 3;
            cpa16(sb + ZG_BH(buf) + row * 80 + seg * 16, Bh + (size_t)(colBase + row) * XC2 + c0 + seg * 8);
            cpa16(sb + ZG_BL(buf) + row * 80 + seg * 16, Bl + (size_t)(colBase + row) * XC2 + c0 + seg * 8);
        }
    };

    const int niter = kslice / 32;
    ldgA(0); stsA(0);
    loadB(0, 0); CP_COMMIT();
    loadB(1, 1); CP_COMMIT();
    ldgA(1);

    uint32_t aoffA = (uint32_t)((lane & 15) * 80 + (lane >> 4) * 16);
    uint32_t aoffB = (uint32_t)(((lane & 7) + ((lane >> 4) << 3)) * 80 + (((lane >> 3) & 1) << 4));

    for (int i = 0; i < niter; i++) {
        int buf = i % 3;
        int abuf = i & 1;
        if (i + 2 < niter)      { loadB(i + 2, (i + 2) % 3); CP_COMMIT(); CP_WAIT2(); }
        else if (i + 1 < niter) { CP_WAIT1(); }
        else                    { CP_WAIT0(); }
        __syncthreads();
        if (i + 1 < niter) {
            stsA(abuf ^ 1);
            if (i + 2 < niter) ldgA(i + 2);
        }

        #pragma unroll
        for (int ks = 0; ks < 2; ks++) {
            uint32_t kso = (uint32_t)(ks * 32);
            uint32_t aH[2][4], aL[2][4], bH[8][2], bL[8][2];
            #pragma unroll
            for (int mt = 0; mt < 2; mt++) {
                uint32_t ro = (uint32_t)((wm * 32 + mt * 16) * 80) + kso;
                ldsm4(aH[mt], sb + ZG_AH(abuf) + ro + aoffA);
                ldsm4(aL[mt], sb + ZG_AL(abuf) + ro + aoffA);
            }
            #pragma unroll
            for (int p = 0; p < 4; p++) {
                uint32_t ro = (uint32_t)((wn * 64 + p * 16) * 80) + kso;
                uint32_t t4[4];
                ldsm4(t4, sb + ZG_BH(buf) + ro + aoffB);
                bH[2*p][0] = t4[0]; bH[2*p][1] = t4[1]; bH[2*p+1][0] = t4[2]; bH[2*p+1][1] = t4[3];
                ldsm4(t4, sb + ZG_BL(buf) + ro + aoffB);
                bL[2*p][0] = t4[0]; bL[2*p][1] = t4[1]; bL[2*p+1][0] = t4[2]; bL[2*p+1][1] = t4[3];
            }
            #pragma unroll
            for (int mt = 0; mt < 2; mt++)
                #pragma unroll
                for (int nt = 0; nt < 8; nt++) {
                    mma16816(acc[mt][nt], aH[mt], bH[nt]);
                    mma16816(acc[mt][nt], aL[mt], bH[nt]);
                    mma16816(acc[mt][nt], aH[mt], bL[nt]);
                }
        }
        __syncthreads();
    }

    float* P = g_part + (size_t)blockIdx.z * B_ * Nfull;
    int row0 = rowBase + wm * 32;
    int col0 = colBase + wn * 64;
    #pragma unroll
    for (int mt = 0; mt < 2; mt++)
        #pragma unroll
        for (int nt = 0; nt < 8; nt++)
            #pragma unroll
            for (int h = 0; h < 2; h++) {
                int r = row0 + mt * 16 + (lane >> 2) + h * 8;
                int cc = col0 + nt * 8 + (lane & 3) * 2;
                *(float2*)&P[(size_t)r * Nfull + cc] =
                    make_float2(acc[mt][nt][h * 2], acc[mt][nt][h * 2 + 1]);
            }
}

// ---------------- K2: k_part ----------------
__global__ void k2_kpart(const float* __restrict__ keys, const float* __restrict__ fc_w)
{
    __shared__ float ks[KK_];
    int m = blockIdx.x, j = threadIdx.x;
    if (j < KK_) ks[j] = keys[m * KK_ + j];
    __syncthreads();
    float acc = 0.f;
    #pragma unroll 8
    for (int i = 0; i < KK_; i++) acc = fmaf(ks[i], fc_w[(XH + i) * HQ + j], acc);
    g_kpart[m * HQ + j] = acc;
}

// ---------------- K4: score LN + gumbel argmax + gather ----------------
__global__ void k4_read(
    const float* __restrict__ x, const float* __restrict__ c,
    const float* __restrict__ prev, const float* __restrict__ gu,
    const float* __restrict__ hmem,
    const float* __restrict__ ln4_g, const float* __restrict__ ln4_b)
{
    int b = blockIdx.x, t = threadIdx.x;
    __shared__ float red[4];
    __shared__ float redf[4];
    __shared__ int   redi[4];
    __shared__ float s_vmax;
    __shared__ int   s_arg;

    float s = g_score[b * M_ + t] - prev[b * M_ + t] * 100.0f;
    float mu = brsum(s, red) * (1.0f / 128.0f);
    float d = s - mu;
    float var = brsum(d * d, red) * (1.0f / 128.0f);
    float sn = d * rsqrtf(var + EPS) * ln4_g[t] + ln4_b[t];
    float u = gu[b * M_ + t];
    float gmb = -logf(1e-20f - logf(1e-20f + u));
    float v = sn + gmb;

    float bv = v; int bidx = t;
    #pragma unroll
    for (int o = 16; o; o >>= 1) {
        float ov = __shfl_xor_sync(0xffffffffu, bv, o);
        int   oi = __shfl_xor_sync(0xffffffffu, bidx, o);
        if (ov > bv || (ov == bv && oi < bidx)) { bv = ov; bidx = oi; }
    }
    __syncthreads();
    if ((t & 31) == 0) { redf[t >> 5] = bv; redi[t >> 5] = bidx; }
    __syncthreads();
    if (t == 0) {
        float fv = redf[0]; int fi = redi[0];
        for (int w = 1; w < 4; w++)
            if (redf[w] > fv || (redf[w] == fv && redi[w] < fi)) { fv = redf[w]; fi = redi[w]; }
        s_vmax = fv; s_arg = fi;
    }
    __syncthreads();
    float e = expf(v - s_vmax);
    float ssum = brsum(e, red);
    float ymax = 1.0f / ssum;
    float w = (1.0f - ymax) + ymax;
    int mi = s_arg;

    const float* hrow = hmem + ((size_t)b * M_ + mi) * H_;
    for (int i = t; i < H_; i += 128) {
        float hv = w * hrow[i];
        g_hentry[b * H_ + i] = hv;
        g_concat[b * XC2 + XH + i] = hv;
        g_concat[b * XC2 + X_ + i] = c[b * H_ + i];
    }
    for (int i = t; i < X_; i += 128) g_concat[b * XC2 + i] = x[b * X_ + i];
}

// ---------------- K6: reduce split-K(8) + bias1 + chunk-LN + sigmoid gate ----------------
__global__ void k6_gate(
    const float* __restrict__ bias1,
    const float* __restrict__ ln3_g, const float* __restrict__ ln3_b)
{
    int ch = blockIdx.x, b = blockIdx.y;
    int t = threadIdx.x;
    __shared__ float red[8];
    float v[4];
    float sum = 0.f;
    #pragma unroll
    for (int q = 0; q < 4; q++) {
        int col = ch * 1024 + q * 256 + t;
        float a = 0.f;
        #pragma unroll
        for (int z = 0; z < 8; z++) a += g_part[((size_t)z * B_ + b) * N2 + col];
        a += bias1[col];
        v[q] = a; sum += a;
    }
    float mu = brsum(sum, red) * (1.0f / 1024.0f);
    float vs = 0.f;
    #pragma unroll
    for (int q = 0; q < 4; q++) { v[q] -= mu; vs += v[q] * v[q]; }
    float var = brsum(vs, red) * (1.0f / 1024.0f);
    float rs = rsqrtf(var + EPS);
    #pragma unroll
    for (int q = 0; q < 4; q++) {
        int col = ch * 1024 + q * 256 + t;
        float g1 = sigm(v[q] * rs * ln3_g[col] + ln3_b[col]);
        g_concat[b * XC2 + X_ + col] *= g1;
    }
}

// ---------------- K8 fused: reduce split-K(4) + bias + chunk-LN(5) + cell + LN + outputs ----
__global__ void k8_fused(
    const float* __restrict__ bias,
    const float* __restrict__ ln1_g, const float* __restrict__ ln1_b,
    const float* __restrict__ c,
    const float* __restrict__ ln2_g, const float* __restrict__ ln2_b,
    float* __restrict__ out)
{
    int b = blockIdx.x, t = threadIdx.x;   // 256 threads
    __shared__ float red[8];
    float zr[5][4];
    #pragma unroll
    for (int ch = 0; ch < 5; ch++) {
        float v[4];
        float sum = 0.f;
        #pragma unroll
        for (int q = 0; q < 4; q++) {
            int col = ch * 1024 + q * 256 + t;
            float a = 0.f;
            #pragma unroll
            for (int z = 0; z < 4; z++) a += g_part[((size_t)z * B_ + b) * N5 + col];
            a += bias[col];
            v[q] = a; sum += a;
        }
        float mu = brsum(sum, red) * (1.0f / 1024.0f);
        float vs = 0.f;
        #pragma unroll
        for (int q = 0; q < 4; q++) { v[q] -= mu; vs += v[q] * v[q]; }
        float var = brsum(vs, red) * (1.0f / 1024.0f);
        float rs = rsqrtf(var + EPS);
        #pragma unroll
        for (int q = 0; q < 4; q++) {
            int col = ch * 1024 + q * 256 + t;
            zr[ch][q] = v[q] * rs * ln1_g[col] + ln1_b[col];
        }
    }
    float nc[4];
    float sum = 0.f;
    #pragma unroll
    for (int q = 0; q < 4; q++) {
        int i = q * 256 + t;
        nc[q] = c[b * H_ + i] * sigm(zr[2][q] + 1.0f) + sigm(zr[0][q]) * tanhf(zr[1][q]);
        sum += nc[q];
    }
    float mu = brsum(sum, red) * (1.0f / 1024.0f);
    float vs = 0.f;
    #pragma unroll
    for (int q = 0; q < 4; q++) { nc[q] -= mu; vs += nc[q] * nc[q]; }
    float var = brsum(vs, red) * (1.0f / 1024.0f);
    float rs = rsqrtf(var + EPS);
    #pragma unroll
    for (int q = 0; q < 4; q++) {
        int i = q * 256 + t;
        float ncn = nc[q] * rs * ln2_g[i] + ln2_b[i];
        out[(size_t)b * N2 + i] = tanhf(ncn) * sigm(zr[3][q]);
        out[(size_t)b * N2 + 1024 + i] = tanhf(g_hentry[b * H_ + i]) * sigm(zr[4][q]);
    }
}

// ---------------- launch ----------------
extern "C" void kernel_launch(void* const* d_in, const int* in_sizes, int n_in,
                              void* d_out, int out_size)
{
    const float* x      = (const float*)d_in[0];
    const float* c      = (const float*)d_in[1];
    const float* hmem   = (const float*)d_in[2];
    const float* u_t    = (const float*)d_in[3];
    const float* prev   = (const float*)d_in[4];
    const float* gu     = (const float*)d_in[5];
    const float* keys   = (const float*)d_in[6];
    const float* vec_a  = (const float*)d_in[7];
    const float* fc_w   = (const float*)d_in[8];
    const float* fc_b   = (const float*)d_in[9];
    const float* W_full = (const float*)d_in[10];
    const float* bias   = (const float*)d_in[11];
    const float* W_full1= (const float*)d_in[12];
    const float* bias1  = (const float*)d_in[13];
    const float* ln1_g  = (const float*)d_in[14];
    const float* ln1_b  = (const float*)d_in[15];
    const float* ln2_g  = (const float*)d_in[16];
    const float* ln2_b  = (const float*)d_in[17];
    const float* ln3_g  = (const float*)d_in[18];
    const float* ln3_b  = (const float*)d_in[19];
    const float* ln4_g  = (const float*)d_in[20];
    const float* ln4_b  = (const float*)d_in[21];
    float* out = (float*)d_out;

    cudaFuncSetAttribute(k3_mma, cudaFuncAttributeMaxDynamicSharedMemorySize, K3_SMEM);
    cudaFuncSetAttribute(gemm_z, cudaFuncAttributeMaxDynamicSharedMemorySize, ZG_SMEM);

    // weight conversion (transpose + bf16 hi/lo split)
    wconv<<<dim3(HQ / 32, H_ / 64), dim3(32, 8)>>>(fc_w + 1600 * HQ, H_, HQ, 0);
    wconv<<<dim3(N2 / 32, XC2 / 64), dim3(32, 8)>>>(W_full1, XC2, N2, 1);
    wconv<<<dim3(N5 / 32, XC2 / 64), dim3(32, 8)>>>(W_full, XC2, N5, 2);

    // sbase GEMM (split-K=8 over 1664)
    k1a_xcu<<<B_, 128>>>(x, c, u_t);
    k1b_sgemm<<<dim3(4, 8), dim3(32, 8)>>>(fc_w);
    k1c_red<<<B_, 256>>>(fc_b);

    k2_kpart<<<M_, 256>>>(keys, fc_w);
    k3_mma<<<B_, 512, K3_SMEM>>>(hmem, vec_a);
    k4_read<<<B_, 128>>>(x, c, prev, gu, hmem, ln4_g, ln4_b);
    // g1 GEMM: [256,2560]@[2560,2048], split-K=8 (kslice 320) -> 256 blocks
    gemm_z<<<dim3(N2 / 128, B_ / 128, 8), 256, ZG_SMEM>>>(1, N2, 320);
    k6_gate<<<dim3(2, B_), 256>>>(bias1, ln3_g, ln3_b);
    // z GEMM: [256,2560]@[2560,5120], split-K=4 (kslice 640) -> 320 blocks
    gemm_z<<<dim3(N5 / 128, B_ / 128, 4), 256, ZG_SMEM>>>(2, N5, 640);
    k8_fused<<<B_, 256>>>(bias, ln1_g, ln1_b, c, ln2_g, ln2_b, out);
}

// round 17
// speedup vs baseline: 1.5693x; 1.0237x over previous
#include <cuda_runtime.h>
#include <cuda_bf16.h>
#include <cstdint>
#include <math.h>

// Shapes (fixed per problem)
#define B_   256
#define X_   512
#define H_   1024
#define M_   128
#define KK_  64
#define XH   1536      // X + H
#define XCU  1664      // X + H + M
#define XC2  2560      // X + 2H
#define HQ   256       // H/4
#define N5   5120      // 5H
#define N2   2048      // 2H
#define EPS  1e-5f

// ---------------- scratch ----------------
__device__ float g_sbase[B_ * HQ];
__device__ float g_kpart[M_ * HQ];
__device__ float g_score[B_ * M_];
__device__ float g_hentry[B_ * H_];
__device__ float g_concat[B_ * XC2];
__device__ float g_xcu[B_ * XCU];
__device__ float g_part[4 * B_ * N5];     // also covers 8*B_*N2
// bf16 hi/lo transposed weights [N, K]
__device__ __nv_bfloat16 g_Whh[HQ * H_];
__device__ __nv_bfloat16 g_Whl[HQ * H_];
__device__ __nv_bfloat16 g_W1h[N2 * XC2];
__device__ __nv_bfloat16 g_W1l[N2 * XC2];
__device__ __nv_bfloat16 g_Wfh[N5 * XC2];
__device__ __nv_bfloat16 g_Wfl[N5 * XC2];

// ---------------- low-level helpers ----------------
__device__ __forceinline__ uint32_t smem_u32(const void* p) {
    uint32_t a;
    asm("{ .reg .u64 t; cvta.to.shared.u64 t, %1; cvt.u32.u64 %0, t; }" : "=r"(a) : "l"(p));
    return a;
}
__device__ __forceinline__ void ldsm4(uint32_t* r, uint32_t a) {
    asm volatile("ldmatrix.sync.aligned.m8n8.x4.shared.b16 {%0,%1,%2,%3}, [%4];"
                 : "=r"(r[0]), "=r"(r[1]), "=r"(r[2]), "=r"(r[3]) : "r"(a));
}
__device__ __forceinline__ void mma16816(float* c, const uint32_t* a, const uint32_t* b) {
    asm volatile("mma.sync.aligned.m16n8k16.row.col.f32.bf16.bf16.f32 "
                 "{%0,%1,%2,%3}, {%4,%5,%6,%7}, {%8,%9}, {%0,%1,%2,%3};"
                 : "+f"(c[0]), "+f"(c[1]), "+f"(c[2]), "+f"(c[3])
                 : "r"(a[0]), "r"(a[1]), "r"(a[2]), "r"(a[3]), "r"(b[0]), "r"(b[1]));
}
__device__ __forceinline__ void cpa16(uint32_t dst, const void* src) {
    asm volatile("cp.async.cg.shared.global [%0], [%1], 16;" :: "r"(dst), "l"(src));
}
#define CP_COMMIT() asm volatile("cp.async.commit_group;" ::: "memory")
#define CP_WAIT2()  asm volatile("cp.async.wait_group 2;" ::: "memory")
#define CP_WAIT1()  asm volatile("cp.async.wait_group 1;" ::: "memory")
#define CP_WAIT0()  asm volatile("cp.async.wait_group 0;" ::: "memory")

__device__ __forceinline__ uint32_t pack_hi2(float x, float y, float& lx, float& ly) {
    __nv_bfloat162 h = __floats2bfloat162_rn(x, y);
    lx = x - __bfloat162float(h.x);
    ly = y - __bfloat162float(h.y);
    return *(uint32_t*)&h;
}
__device__ __forceinline__ uint32_t pack2(float x, float y) {
    __nv_bfloat162 h = __floats2bfloat162_rn(x, y);
    return *(uint32_t*)&h;
}
__device__ __forceinline__ float sigm(float x) { return 1.0f / (1.0f + expf(-x)); }

__device__ __forceinline__ float brsum(float v, float* red) {
    int lane = threadIdx.x & 31, w = threadIdx.x >> 5;
    int nw = blockDim.x >> 5;
    #pragma unroll
    for (int o = 16; o; o >>= 1) v += __shfl_xor_sync(0xffffffffu, v, o);
    __syncthreads();
    if (lane == 0) red[w] = v;
    __syncthreads();
    float s = 0.f;
    for (int i = 0; i < nw; i++) s += red[i];
    return s;
}

// ---------------- weight transpose + bf16 hi/lo split ----------------
__global__ void wconv(const float* __restrict__ W, int K, int N, int which)
{
    __nv_bfloat16 *Whi, *Wlo;
    if (which == 0)      { Whi = g_Whh; Wlo = g_Whl; }
    else if (which == 1) { Whi = g_W1h; Wlo = g_W1l; }
    else                 { Whi = g_Wfh; Wlo = g_Wfl; }
    __shared__ float t[64][33];
    int nb = blockIdx.x * 32, kb = blockIdx.y * 64;
    int tx = threadIdx.x, ty = threadIdx.y;
    for (int r = ty; r < 64; r += 8)
        t[r][tx] = W[(size_t)(kb + r) * N + nb + tx];
    __syncthreads();
    for (int r = ty; r < 32; r += 8) {
        float v0 = t[2 * tx][r], v1 = t[2 * tx + 1][r];
        float l0, l1;
        uint32_t hp = pack_hi2(v0, v1, l0, l1);
        uint32_t lp = pack2(l0, l1);
        size_t o = (size_t)(nb + r) * K + kb + 2 * tx;
        *(uint32_t*)&Whi[o] = hp;
        *(uint32_t*)&Wlo[o] = lp;
    }
}

// ---------------- K1a: build g_xcu = [x | c | u_norm] ----------------
__global__ void k1a_xcu(const float* __restrict__ x, const float* __restrict__ c,
                        const float* __restrict__ u_t)
{
    int b = blockIdx.x, t = threadIdx.x;  // 128 threads
    __shared__ float red[4];
    float uv = u_t[b * M_ + t];
    float s = brsum(uv * uv, red);
    float inv = 1.0f / fmaxf(sqrtf(s), 1e-12f);
    float* row = g_xcu + (size_t)b * XCU;
    for (int i = t; i < X_; i += 128) row[i] = x[b * X_ + i];
    for (int i = t; i < H_; i += 128) row[X_ + i] = c[b * H_ + i];
    row[XH + t] = uv * inv;
}

// ---------------- K1b: split-K SGEMM  g_part[z] = g_xcu[:,ks] @ fc_w'[ks,:] ----------------
__global__ __launch_bounds__(256) void k1b_sgemm(const float* __restrict__ fc_w)
{
    __shared__ float As[16][64];
    __shared__ float Bs[16][256];
    int rowBase = blockIdx.x * 64;
    int kStart = blockIdx.y * 208;
    int tx = threadIdx.x, ty = threadIdx.y;
    int tid = ty * 32 + tx;

    float acc[8][8];
    #pragma unroll
    for (int i = 0; i < 8; i++)
        #pragma unroll
        for (int j = 0; j < 8; j++) acc[i][j] = 0.f;

    int am = tid >> 2;
    int ak = (tid & 3) * 4;
    int bc = (tid & 63) * 4;
    int br0 = tid >> 6;

    for (int k0 = 0; k0 < 208; k0 += 16) {
        float4 av = *(const float4*)&g_xcu[(size_t)(rowBase + am) * XCU + kStart + k0 + ak];
        As[ak + 0][am] = av.x; As[ak + 1][am] = av.y;
        As[ak + 2][am] = av.z; As[ak + 3][am] = av.w;
        #pragma unroll
        for (int r = 0; r < 4; r++) {
            int kk = r * 4 + br0;
            int krow = kStart + k0 + kk;
            int frow = (krow < XH) ? krow : krow + 1088;   // u segment -> fc_w rows 2624+
            *(float4*)&Bs[kk][bc] = *(const float4*)&fc_w[(size_t)frow * HQ + bc];
        }
        __syncthreads();
        #pragma unroll
        for (int k = 0; k < 16; k++) {
            float4 a0 = *(float4*)&As[k][ty * 8];
            float4 a1 = *(float4*)&As[k][ty * 8 + 4];
            float4 b0 = *(float4*)&Bs[k][tx * 8];
            float4 b1 = *(float4*)&Bs[k][tx * 8 + 4];
            float a[8] = {a0.x, a0.y, a0.z, a0.w, a1.x, a1.y, a1.z, a1.w};
            float b[8] = {b0.x, b0.y, b0.z, b0.w, b1.x, b1.y, b1.z, b1.w};
            #pragma unroll
            for (int i = 0; i < 8; i++)
                #pragma unroll
                for (int j = 0; j < 8; j++)
                    acc[i][j] = fmaf(a[i], b[j], acc[i][j]);
        }
        __syncthreads();
    }

    float* P = g_part + (size_t)blockIdx.y * B_ * HQ;
    #pragma unroll
    for (int i = 0; i < 8; i++) {
        int row = rowBase + ty * 8 + i;
        *(float4*)&P[(size_t)row * HQ + tx * 8]     = make_float4(acc[i][0], acc[i][1], acc[i][2], acc[i][3]);
        *(float4*)&P[(size_t)row * HQ + tx * 8 + 4] = make_float4(acc[i][4], acc[i][5], acc[i][6], acc[i][7]);
    }
}

// ---------------- K1c: reduce 8 partials + fc_b -> g_sbase ----------------
__global__ void k1c_red(const float* __restrict__ fc_b)
{
    int b = blockIdx.x, j = threadIdx.x;
    float a = fc_b[j];
    #pragma unroll
    for (int z = 0; z < 8; z++) a += g_part[((size_t)z * B_ + b) * HQ + j];
    g_sbase[b * HQ + j] = a;
}

// ================= K3: score GEMM (bf16x3), 64x64 warp tiles =================
// tile 128x256, BK=32, 256 threads (8 warps, 2x4), warp 64x64. stride 80 B.
#define K3_AH(b) ((b) * 10240)
#define K3_AL(b) (20480 + (b) * 10240)
#define K3_BH(b) (40960 + (b) * 40960)
#define K3_BL(b) (61440 + (b) * 40960)
#define K3_RED   163840
#define K3_SMEM  165888

__global__ __launch_bounds__(256, 1) void k3_mma(
    const float* __restrict__ hmem, const float* __restrict__ vec_a)
{
    extern __shared__ char sm[];
    uint32_t sb = smem_u32(sm);
    int tid = threadIdx.x, lane = tid & 31, wid = tid >> 5;
    int wm = wid >> 2, wn = wid & 3;   // 2 x 4 warps, each 64x64
    int rowBase = blockIdx.x * 128;

    float acc[4][8][4];
    #pragma unroll
    for (int i = 0; i < 4; i++)
        #pragma unroll
        for (int j = 0; j < 8; j++)
            #pragma unroll
            for (int q = 0; q < 4; q++) acc[i][j][q] = 0.f;

    int arow = tid >> 3, aq = tid & 7;
    float4 aReg[4];
    auto ldgA = [&](int i) {
        int c0 = i * 32;
        #pragma unroll
        for (int it = 0; it < 4; it++) {
            int row = arow + it * 32;
            aReg[it] = *(const float4*)&hmem[(size_t)(rowBase + row) * H_ + c0 + aq * 4];
        }
    };
    auto stsA = [&](int buf) {
        #pragma unroll
        for (int it = 0; it < 4; it++) {
            int row = arow + it * 32;
            float4 v = aReg[it];
            float lx, ly, lz, lw;
            uint32_t h0 = pack_hi2(v.x, v.y, lx, ly);
            uint32_t h1 = pack_hi2(v.z, v.w, lz, lw);
            char* ah = sm + K3_AH(buf) + row * 80 + aq * 8;
            char* al = sm + K3_AL(buf) + row * 80 + aq * 8;
            *(uint32_t*)ah = h0; *(uint32_t*)(ah + 4) = h1;
            *(uint32_t*)al = pack2(lx, ly); *(uint32_t*)(al + 4) = pack2(lz, lw);
        }
    };
    auto loadB = [&](int i, int buf) {
        int c0 = i * 32;
        #pragma unroll
        for (int it = 0; it < 4; it++) {
            int idx = tid + it * 256;
            int row = idx >> 2, seg = idx & 3;
            cpa16(sb + K3_BH(buf) + row * 80 + seg * 16, g_Whh + (size_t)row * H_ + c0 + seg * 8);
            cpa16(sb + K3_BL(buf) + row * 80 + seg * 16, g_Whl + (size_t)row * H_ + c0 + seg * 8);
        }
    };

    const int niter = H_ / 32;   // 32
    ldgA(0); stsA(0);
    loadB(0, 0); CP_COMMIT();
    loadB(1, 1); CP_COMMIT();
    ldgA(1);

    uint32_t aoffA = (uint32_t)((lane & 15) * 80 + (lane >> 4) * 16);
    uint32_t aoffB = (uint32_t)(((lane & 7) + ((lane >> 4) << 3)) * 80 + (((lane >> 3) & 1) << 4));

    for (int i = 0; i < niter; i++) {
        int buf = i % 3;       // B buffer
        int abuf = i & 1;      // A buffer
        if (i + 2 < niter)      { loadB(i + 2, (i + 2) % 3); CP_COMMIT(); CP_WAIT2(); }
        else if (i + 1 < niter) { CP_WAIT1(); }
        else                    { CP_WAIT0(); }
        __syncthreads();
        if (i + 1 < niter) {
            stsA(abuf ^ 1);
            if (i + 2 < niter) ldgA(i + 2);
        }

        #pragma unroll
        for (int ks = 0; ks < 2; ks++) {
            uint32_t kso = (uint32_t)(ks * 32);
            uint32_t aH[4][4], aL[4][4], bH[8][2], bL[8][2];
            #pragma unroll
            for (int mt = 0; mt < 4; mt++) {
                uint32_t ro = (uint32_t)((wm * 64 + mt * 16) * 80) + kso;
                ldsm4(aH[mt], sb + K3_AH(abuf) + ro + aoffA);
                ldsm4(aL[mt], sb + K3_AL(abuf) + ro + aoffA);
            }
            #pragma unroll
            for (int p = 0; p < 4; p++) {
                uint32_t ro = (uint32_t)((wn * 64 + p * 16) * 80) + kso;
                uint32_t t4[4];
                ldsm4(t4, sb + K3_BH(buf) + ro + aoffB);
                bH[2*p][0] = t4[0]; bH[2*p][1] = t4[1]; bH[2*p+1][0] = t4[2]; bH[2*p+1][1] = t4[3];
                ldsm4(t4, sb + K3_BL(buf) + ro + aoffB);
                bL[2*p][0] = t4[0]; bL[2*p][1] = t4[1]; bL[2*p+1][0] = t4[2]; bL[2*p+1][1] = t4[3];
            }
            #pragma unroll
            for (int mt = 0; mt < 4; mt++)
                #pragma unroll
                for (int nt = 0; nt < 8; nt++) {
                    mma16816(acc[mt][nt], aH[mt], bH[nt]);
                    mma16816(acc[mt][nt], aL[mt], bH[nt]);
                    mma16816(acc[mt][nt], aH[mt], bL[nt]);
                }
        }
        __syncthreads();
    }

    // epilogue: + sbase + kpart, tanh, dot vec_a, reduce over 256 cols
    float* sred = (float*)(sm + K3_RED);   // [128][4]
    int bi = rowBase >> 7;
    const float* sb_row = g_sbase + bi * HQ;
    #pragma unroll
    for (int mt = 0; mt < 4; mt++) {
        #pragma unroll
        for (int h = 0; h < 2; h++) {
            int rl = wm * 64 + mt * 16 + (lane >> 2) + h * 8;  // 0..127 = m index
            const float* kp_row = g_kpart + rl * HQ;
            float rsum = 0.f;
            #pragma unroll
            for (int nt = 0; nt < 8; nt++) {
                #pragma unroll
                for (int j = 0; j < 2; j++) {
                    int col = wn * 64 + nt * 8 + (lane & 3) * 2 + j;
                    float v = acc[mt][nt][h * 2 + j] + sb_row[col] + kp_row[col];
                    rsum = fmaf(tanhf(v), vec_a[col], rsum);
                }
            }
            rsum += __shfl_xor_sync(0xffffffffu, rsum, 1);
            rsum += __shfl_xor_sync(0xffffffffu, rsum, 2);
            if ((lane & 3) == 0) sred[rl * 4 + wn] = rsum;
        }
    }
    __syncthreads();
    if (tid < 128)
        g_score[rowBase + tid] = sred[tid * 4] + sred[tid * 4 + 1]
                               + sred[tid * 4 + 2] + sred[tid * 4 + 3];
}

// ================= z GEMMs: bf16x3, 64x64 warp tiles (128 threads, 2 CTA/SM) =================
#define ZG_AH(b) ((b) * 10240)
#define ZG_AL(b) (20480 + (b) * 10240)
#define ZG_BH(b) (40960 + (b) * 20480)
#define ZG_BL(b) (51200 + (b) * 20480)
#define ZG_SMEM  102400

__global__ __launch_bounds__(128, 2) void gemm_z(int which, int Nfull, int kslice)
{
    extern __shared__ char sm[];
    uint32_t sb = smem_u32(sm);
    const __nv_bfloat16 *Bh, *Bl;
    if (which == 1) { Bh = g_W1h; Bl = g_W1l; }
    else            { Bh = g_Wfh; Bl = g_Wfl; }
    int tid = threadIdx.x, lane = tid & 31, wid = tid >> 5;
    int wm = wid >> 1, wn = wid & 1;   // 2 x 2 warps, each 64x64
    int rowBase = blockIdx.y * 128;
    int colBase = blockIdx.x * 128;
    int kStart  = blockIdx.z * kslice;

    float acc[4][8][4];
    #pragma unroll
    for (int i = 0; i < 4; i++)
        #pragma unroll
        for (int j = 0; j < 8; j++)
            #pragma unroll
            for (int q = 0; q < 4; q++) acc[i][j][q] = 0.f;

    int arow = tid >> 3, aq = tid & 7;
    float4 aReg[8];
    auto ldgA = [&](int i) {
        int c0 = kStart + i * 32;
        #pragma unroll
        for (int it = 0; it < 8; it++) {
            int row = arow + it * 16;
            aReg[it] = *(const float4*)&g_concat[(size_t)(rowBase + row) * XC2 + c0 + aq * 4];
        }
    };
    auto stsA = [&](int buf) {
        #pragma unroll
        for (int it = 0; it < 8; it++) {
            int row = arow + it * 16;
            float4 v = aReg[it];
            float lx, ly, lz, lw;
            uint32_t h0 = pack_hi2(v.x, v.y, lx, ly);
            uint32_t h1 = pack_hi2(v.z, v.w, lz, lw);
            char* ah = sm + ZG_AH(buf) + row * 80 + aq * 8;
            char* al = sm + ZG_AL(buf) + row * 80 + aq * 8;
            *(uint32_t*)ah = h0; *(uint32_t*)(ah + 4) = h1;
            *(uint32_t*)al = pack2(lx, ly); *(uint32_t*)(al + 4) = pack2(lz, lw);
        }
    };
    auto loadB = [&](int i, int buf) {
        int c0 = kStart + i * 32;
        #pragma unroll
        for (int it = 0; it < 4; it++) {
            int idx = tid + it * 128;
            int row = idx >> 2, seg = idx & 3;
            cpa16(sb + ZG_BH(buf) + row * 80 + seg * 16, Bh + (size_t)(colBase + row) * XC2 + c0 + seg * 8);
            cpa16(sb + ZG_BL(buf) + row * 80 + seg * 16, Bl + (size_t)(colBase + row) * XC2 + c0 + seg * 8);
        }
    };

    const int niter = kslice / 32;
    ldgA(0); stsA(0);
    loadB(0, 0); CP_COMMIT();
    loadB(1, 1); CP_COMMIT();
    ldgA(1);

    uint32_t aoffA = (uint32_t)((lane & 15) * 80 + (lane >> 4) * 16);
    uint32_t aoffB = (uint32_t)(((lane & 7) + ((lane >> 4) << 3)) * 80 + (((lane >> 3) & 1) << 4));

    for (int i = 0; i < niter; i++) {
        int buf = i % 3;
        int abuf = i & 1;
        if (i + 2 < niter)      { loadB(i + 2, (i + 2) % 3); CP_COMMIT(); CP_WAIT2(); }
        else if (i + 1 < niter) { CP_WAIT1(); }
        else                    { CP_WAIT0(); }
        __syncthreads();
        if (i + 1 < niter) {
            stsA(abuf ^ 1);
            if (i + 2 < niter) ldgA(i + 2);
        }

        #pragma unroll
        for (int ks = 0; ks < 2; ks++) {
            uint32_t kso = (uint32_t)(ks * 32);
            uint32_t aH[4][4], aL[4][4], bH[8][2], bL[8][2];
            #pragma unroll
            for (int mt = 0; mt < 4; mt++) {
                uint32_t ro = (uint32_t)((wm * 64 + mt * 16) * 80) + kso;
                ldsm4(aH[mt], sb + ZG_AH(abuf) + ro + aoffA);
                ldsm4(aL[mt], sb + ZG_AL(abuf) + ro + aoffA);
            }
            #pragma unroll
            for (int p = 0; p < 4; p++) {
                uint32_t ro = (uint32_t)((wn * 64 + p * 16) * 80) + kso;
                uint32_t t4[4];
                ldsm4(t4, sb + ZG_BH(buf) + ro + aoffB);
                bH[2*p][0] = t4[0]; bH[2*p][1] = t4[1]; bH[2*p+1][0] = t4[2]; bH[2*p+1][1] = t4[3];
                ldsm4(t4, sb + ZG_BL(buf) + ro + aoffB);
                bL[2*p][0] = t4[0]; bL[2*p][1] = t4[1]; bL[2*p+1][0] = t4[2]; bL[2*p+1][1] = t4[3];
            }
            #pragma unroll
            for (int mt = 0; mt < 4; mt++)
                #pragma unroll
                for (int nt = 0; nt < 8; nt++) {
                    mma16816(acc[mt][nt], aH[mt], bH[nt]);
                    mma16816(acc[mt][nt], aL[mt], bH[nt]);
                    mma16816(acc[mt][nt], aH[mt], bL[nt]);
                }
        }
        __syncthreads();
    }

    float* P = g_part + (size_t)blockIdx.z * B_ * Nfull;
    int row0 = rowBase + wm * 64;
    int col0 = colBase + wn * 64;
    #pragma unroll
    for (int mt = 0; mt < 4; mt++)
        #pragma unroll
        for (int nt = 0; nt < 8; nt++)
            #pragma unroll
            for (int h = 0; h < 2; h++) {
                int r = row0 + mt * 16 + (lane >> 2) + h * 8;
                int cc = col0 + nt * 8 + (lane & 3) * 2;
                *(float2*)&P[(size_t)r * Nfull + cc] =
                    make_float2(acc[mt][nt][h * 2], acc[mt][nt][h * 2 + 1]);
            }
}

// ---------------- K2: k_part ----------------
__global__ void k2_kpart(const float* __restrict__ keys, const float* __restrict__ fc_w)
{
    __shared__ float ks[KK_];
    int m = blockIdx.x, j = threadIdx.x;
    if (j < KK_) ks[j] = keys[m * KK_ + j];
    __syncthreads();
    float acc = 0.f;
    #pragma unroll 8
    for (int i = 0; i < KK_; i++) acc = fmaf(ks[i], fc_w[(XH + i) * HQ + j], acc);
    g_kpart[m * HQ + j] = acc;
}

// ---------------- K4: score LN + gumbel argmax + gather ----------------
__global__ void k4_read(
    const float* __restrict__ x, const float* __restrict__ c,
    const float* __restrict__ prev, const float* __restrict__ gu,
    const float* __restrict__ hmem,
    const float* __restrict__ ln4_g, const float* __restrict__ ln4_b)
{
    int b = blockIdx.x, t = threadIdx.x;
    __shared__ float red[4];
    __shared__ float redf[4];
    __shared__ int   redi[4];
    __shared__ float s_vmax;
    __shared__ int   s_arg;

    float s = g_score[b * M_ + t] - prev[b * M_ + t] * 100.0f;
    float mu = brsum(s, red) * (1.0f / 128.0f);
    float d = s - mu;
    float var = brsum(d * d, red) * (1.0f / 128.0f);
    float sn = d * rsqrtf(var + EPS) * ln4_g[t] + ln4_b[t];
    float u = gu[b * M_ + t];
    float gmb = -logf(1e-20f - logf(1e-20f + u));
    float v = sn + gmb;

    float bv = v; int bidx = t;
    #pragma unroll
    for (int o = 16; o; o >>= 1) {
        float ov = __shfl_xor_sync(0xffffffffu, bv, o);
        int   oi = __shfl_xor_sync(0xffffffffu, bidx, o);
        if (ov > bv || (ov == bv && oi < bidx)) { bv = ov; bidx = oi; }
    }
    __syncthreads();
    if ((t & 31) == 0) { redf[t >> 5] = bv; redi[t >> 5] = bidx; }
    __syncthreads();
    if (t == 0) {
        float fv = redf[0]; int fi = redi[0];
        for (int w = 1; w < 4; w++)
            if (redf[w] > fv || (redf[w] == fv && redi[w] < fi)) { fv = redf[w]; fi = redi[w]; }
        s_vmax = fv; s_arg = fi;
    }
    __syncthreads();
    float e = expf(v - s_vmax);
    float ssum = brsum(e, red);
    float ymax = 1.0f / ssum;
    float w = (1.0f - ymax) + ymax;
    int mi = s_arg;

    const float* hrow = hmem + ((size_t)b * M_ + mi) * H_;
    for (int i = t; i < H_; i += 128) {
        float hv = w * hrow[i];
        g_hentry[b * H_ + i] = hv;
        g_concat[b * XC2 + XH + i] = hv;
        g_concat[b * XC2 + X_ + i] = c[b * H_ + i];
    }
    for (int i = t; i < X_; i += 128) g_concat[b * XC2 + i] = x[b * X_ + i];
}

// ---------------- K6: reduce split-K(8) + bias1 + chunk-LN + sigmoid gate ----------------
__global__ void k6_gate(
    const float* __restrict__ bias1,
    const float* __restrict__ ln3_g, const float* __restrict__ ln3_b)
{
    int ch = blockIdx.x, b = blockIdx.y;
    int t = threadIdx.x;
    __shared__ float red[8];
    float v[4];
    float sum = 0.f;
    #pragma unroll
    for (int q = 0; q < 4; q++) {
        int col = ch * 1024 + q * 256 + t;
        float a = 0.f;
        #pragma unroll
        for (int z = 0; z < 8; z++) a += g_part[((size_t)z * B_ + b) * N2 + col];
        a += bias1[col];
        v[q] = a; sum += a;
    }
    float mu = brsum(sum, red) * (1.0f / 1024.0f);
    float vs = 0.f;
    #pragma unroll
    for (int q = 0; q < 4; q++) { v[q] -= mu; vs += v[q] * v[q]; }
    float var = brsum(vs, red) * (1.0f / 1024.0f);
    float rs = rsqrtf(var + EPS);
    #pragma unroll
    for (int q = 0; q < 4; q++) {
        int col = ch * 1024 + q * 256 + t;
        float g1 = sigm(v[q] * rs * ln3_g[col] + ln3_b[col]);
        g_concat[b * XC2 + X_ + col] *= g1;
    }
}

// ---------------- K8 fused: reduce split-K(4) + bias + chunk-LN(5) + cell + LN + outputs ----
__global__ void k8_fused(
    const float* __restrict__ bias,
    const float* __restrict__ ln1_g, const float* __restrict__ ln1_b,
    const float* __restrict__ c,
    const float* __restrict__ ln2_g, const float* __restrict__ ln2_b,
    float* __restrict__ out)
{
    int b = blockIdx.x, t = threadIdx.x;   // 256 threads
    __shared__ float red[8];
    float zr[5][4];
    #pragma unroll
    for (int ch = 0; ch < 5; ch++) {
        float v[4];
        float sum = 0.f;
        #pragma unroll
        for (int q = 0; q < 4; q++) {
            int col = ch * 1024 + q * 256 + t;
            float a = 0.f;
            #pragma unroll
            for (int z = 0; z < 4; z++) a += g_part[((size_t)z * B_ + b) * N5 + col];
            a += bias[col];
            v[q] = a; sum += a;
        }
        float mu = brsum(sum, red) * (1.0f / 1024.0f);
        float vs = 0.f;
        #pragma unroll
        for (int q = 0; q < 4; q++) { v[q] -= mu; vs += v[q] * v[q]; }
        float var = brsum(vs, red) * (1.0f / 1024.0f);
        float rs = rsqrtf(var + EPS);
        #pragma unroll
        for (int q = 0; q < 4; q++) {
            int col = ch * 1024 + q * 256 + t;
            zr[ch][q] = v[q] * rs * ln1_g[col] + ln1_b[col];
        }
    }
    float nc[4];
    float sum = 0.f;
    #pragma unroll
    for (int q = 0; q < 4; q++) {
        int i = q * 256 + t;
        nc[q] = c[b * H_ + i] * sigm(zr[2][q] + 1.0f) + sigm(zr[0][q]) * tanhf(zr[1][q]);
        sum += nc[q];
    }
    float mu = brsum(sum, red) * (1.0f / 1024.0f);
    float vs = 0.f;
    #pragma unroll
    for (int q = 0; q < 4; q++) { nc[q] -= mu; vs += nc[q] * nc[q]; }
    float var = brsum(vs, red) * (1.0f / 1024.0f);
    float rs = rsqrtf(var + EPS);
    #pragma unroll
    for (int q = 0; q < 4; q++) {
        int i = q * 256 + t;
        float ncn = nc[q] * rs * ln2_g[i] + ln2_b[i];
        out[(size_t)b * N2 + i] = tanhf(ncn) * sigm(zr[3][q]);
        out[(size_t)b * N2 + 1024 + i] = tanhf(g_hentry[b * H_ + i]) * sigm(zr[4][q]);
    }
}

// ---------------- launch ----------------
extern "C" void kernel_launch(void* const* d_in, const int* in_sizes, int n_in,
                              void* d_out, int out_size)
{
    const float* x      = (const float*)d_in[0];
    const float* c      = (const float*)d_in[1];
    const float* hmem   = (const float*)d_in[2];
    const float* u_t    = (const float*)d_in[3];
    const float* prev   = (const float*)d_in[4];
    const float* gu     = (const float*)d_in[5];
    const float* keys   = (const float*)d_in[6];
    const float* vec_a  = (const float*)d_in[7];
    const float* fc_w   = (const float*)d_in[8];
    const float* fc_b   = (const float*)d_in[9];
    const float* W_full = (const float*)d_in[10];
    const float* bias   = (const float*)d_in[11];
    const float* W_full1= (const float*)d_in[12];
    const float* bias1  = (const float*)d_in[13];
    const float* ln1_g  = (const float*)d_in[14];
    const float* ln1_b  = (const float*)d_in[15];
    const float* ln2_g  = (const float*)d_in[16];
    const float* ln2_b  = (const float*)d_in[17];
    const float* ln3_g  = (const float*)d_in[18];
    const float* ln3_b  = (const float*)d_in[19];
    const float* ln4_g  = (const float*)d_in[20];
    const float* ln4_b  = (const float*)d_in[21];
    float* out = (float*)d_out;

    cudaFuncSetAttribute(k3_mma, cudaFuncAttributeMaxDynamicSharedMemorySize, K3_SMEM);
    cudaFuncSetAttribute(gemm_z, cudaFuncAttributeMaxDynamicSharedMemorySize, ZG_SMEM);

    // weight conversion (transpose + bf16 hi/lo split)
    wconv<<<dim3(HQ / 32, H_ / 64), dim3(32, 8)>>>(fc_w + 1600 * HQ, H_, HQ, 0);
    wconv<<<dim3(N2 / 32, XC2 / 64), dim3(32, 8)>>>(W_full1, XC2, N2, 1);
    wconv<<<dim3(N5 / 32, XC2 / 64), dim3(32, 8)>>>(W_full, XC2, N5, 2);

    // sbase GEMM (split-K=8 over 1664)
    k1a_xcu<<<B_, 128>>>(x, c, u_t);
    k1b_sgemm<<<dim3(4, 8), dim3(32, 8)>>>(fc_w);
    k1c_red<<<B_, 256>>>(fc_b);

    k2_kpart<<<M_, 256>>>(keys, fc_w);
    k3_mma<<<B_, 256, K3_SMEM>>>(hmem, vec_a);
    k4_read<<<B_, 128>>>(x, c, prev, gu, hmem, ln4_g, ln4_b);
    // g1 GEMM: [256,2560]@[2560,2048], split-K=8 (kslice 320) -> 256 blocks
    gemm_z<<<dim3(N2 / 128, B_ / 128, 8), 128, ZG_SMEM>>>(1, N2, 320);
    k6_gate<<<dim3(2, B_), 256>>>(bias1, ln3_g, ln3_b);
    // z GEMM: [256,2560]@[2560,5120], split-K=4 (kslice 640) -> 320 blocks
    gemm_z<<<dim3(N5 / 128, B_ / 128, 4), 128, ZG_SMEM>>>(2, N5, 640);
    k8_fused<<<B_, 256>>>(bias, ln1_g, ln1_b, c, ln2_g, ln2_b, out);
}